// round 1
// baseline (speedup 1.0000x reference)
#include <cuda_runtime.h>
#include <cstdint>

#define BSZ 4
#define LQ  512
#define LK  2048
#define DM  1024
#define NH  16
#define DK  64
#define QT  8
#define VOCAB_B 900

// ---------------- scratch (static device memory; no runtime alloc) ----------
__device__ float g_Qp[BSZ * LQ * DM];   // projected Q, (b*LQ+q, dm)
__device__ float g_Kp[BSZ * LK * DM];   // projected K, (b*LK+k, dm)
__device__ float g_Vp[BSZ * LK * DM];   // projected V
__device__ float g_Ao[BSZ * LQ * DM];   // attention output (concat heads)

// ---------------------------------------------------------------------------
// C[m][n] = sum_k A[m][k] * B[n][k] + bias[n]
// A: [M,K] row-major, B: [N,K] row-major (i.e. computes A @ B^T + bias)
// Tiles: 128x128x16, 256 threads, 8x8 per thread. M,N,K multiples of 128/16.
// ---------------------------------------------------------------------------
__global__ __launch_bounds__(256) void sgemm_bt_kernel(
    const float* __restrict__ A, const float* __restrict__ B,
    const float* __restrict__ bias, float* __restrict__ C,
    int M, int N, int K)
{
    const int BM = 128, BN = 128, BK = 16;
    __shared__ float As[BK][BM];
    __shared__ float Bs[BK][BN];

    const int tid = threadIdx.x;
    const int tx = tid & 15;        // column group
    const int ty = tid >> 4;        // row group
    const int m0 = blockIdx.y * BM;
    const int n0 = blockIdx.x * BN;

    float acc[8][8];
#pragma unroll
    for (int i = 0; i < 8; i++)
#pragma unroll
        for (int j = 0; j < 8; j++) acc[i][j] = 0.f;

    for (int k0 = 0; k0 < K; k0 += BK) {
        // load tiles (transposed stores for coalesced compute reads)
#pragma unroll
        for (int t = 0; t < 2; t++) {
            int idx = tid + t * 256;          // 0..511
            int r   = idx >> 2;               // 0..127
            int c4  = (idx & 3) * 4;          // 0,4,8,12
            float4 a = *(const float4*)&A[(size_t)(m0 + r) * K + k0 + c4];
            As[c4 + 0][r] = a.x; As[c4 + 1][r] = a.y;
            As[c4 + 2][r] = a.z; As[c4 + 3][r] = a.w;
            float4 b = *(const float4*)&B[(size_t)(n0 + r) * K + k0 + c4];
            Bs[c4 + 0][r] = b.x; Bs[c4 + 1][r] = b.y;
            Bs[c4 + 2][r] = b.z; Bs[c4 + 3][r] = b.w;
        }
        __syncthreads();

#pragma unroll
        for (int kk = 0; kk < BK; kk++) {
            float ra[8], rb[8];
            *(float4*)&ra[0] = *(const float4*)&As[kk][ty * 8];
            *(float4*)&ra[4] = *(const float4*)&As[kk][ty * 8 + 4];
            *(float4*)&rb[0] = *(const float4*)&Bs[kk][tx * 8];
            *(float4*)&rb[4] = *(const float4*)&Bs[kk][tx * 8 + 4];
#pragma unroll
            for (int i = 0; i < 8; i++)
#pragma unroll
                for (int j = 0; j < 8; j++) acc[i][j] += ra[i] * rb[j];
        }
        __syncthreads();
    }

#pragma unroll
    for (int i = 0; i < 8; i++) {
        int m = m0 + ty * 8 + i;
#pragma unroll
        for (int j = 0; j < 8; j += 4) {
            int n = n0 + tx * 8 + j;
            float4 o;
            o.x = acc[i][j + 0] + bias[n + 0];
            o.y = acc[i][j + 1] + bias[n + 1];
            o.z = acc[i][j + 2] + bias[n + 2];
            o.w = acc[i][j + 3] + bias[n + 3];
            *(float4*)&C[(size_t)m * N + n] = o;
        }
    }
}

// ---------------------------------------------------------------------------
// Attention: one CTA per (head, 8-query tile, batch). 256 threads.
// scores -> +bias (table gather) -> mask -> softmax -> P @ V
// ---------------------------------------------------------------------------
__global__ __launch_bounds__(256) void attn_kernel(
    const float* __restrict__ Qp, const float* __restrict__ Kp,
    const float* __restrict__ Vp, const int* __restrict__ b_idx,
    const int* __restrict__ mask, const float* __restrict__ b_table,
    float* __restrict__ Ao)
{
    const int h  = blockIdx.x;
    const int q0 = blockIdx.y * QT;
    const int b  = blockIdx.z;
    const int tid = threadIdx.x;

    extern __shared__ float smem[];
    float* qs   = smem;                    // QT*DK            = 512
    float* bt   = qs + QT * DK;            // VOCAB_B          = 900
    float* sc   = bt + VOCAB_B;            // QT*LK            = 16384
    float* outb = sc + QT * LK;            // 4*QT*DK          = 2048
    __shared__ float sinv[QT];

    // stage q vectors (float4) and bias column for this head
    for (int i = tid; i < QT * DK / 4; i += 256) {
        int qi = i >> 4, c4 = i & 15;
        ((float4*)qs)[qi * 16 + c4] =
            *(const float4*)&Qp[((size_t)(b * LQ + q0 + qi)) * DM + h * DK + c4 * 4];
    }
    for (int i = tid; i < VOCAB_B; i += 256) bt[i] = b_table[i * NH + h];
    __syncthreads();

    // ---- scores: each thread owns k = tid, tid+256, ... (8 iterations) ----
    for (int k = tid; k < LK; k += 256) {
        const float4* kr = (const float4*)&Kp[((size_t)(b * LK + k)) * DM + h * DK];
        float dot[QT];
#pragma unroll
        for (int qi = 0; qi < QT; qi++) dot[qi] = 0.f;
#pragma unroll
        for (int j = 0; j < 16; j++) {
            float4 kv = kr[j];
#pragma unroll
            for (int qi = 0; qi < QT; qi++) {
                float4 q4 = *(const float4*)&qs[qi * DK + j * 4];
                dot[qi] += kv.x * q4.x + kv.y * q4.y + kv.z * q4.z + kv.w * q4.w;
            }
        }
        int boff = (b * LQ + q0) * LK + k;
#pragma unroll
        for (int qi = 0; qi < QT; qi++) {
            int idx = b_idx[boff + qi * LK];
            int mk  = mask[boff + qi * LK];
            float s = (mk == 0) ? -1e9f : (dot[qi] * 0.125f + bt[idx]);
            sc[qi * LK + k] = s;
        }
    }
    __syncthreads();

    // ---- softmax: warp w handles query qi = w ----
    {
        const int w = tid >> 5, lane = tid & 31;
        float m = -3.4e38f;
        for (int k = lane; k < LK; k += 32) m = fmaxf(m, sc[w * LK + k]);
#pragma unroll
        for (int o = 16; o; o >>= 1) m = fmaxf(m, __shfl_xor_sync(0xffffffffu, m, o));
        float s = 0.f;
        for (int k = lane; k < LK; k += 32) {
            float e = __expf(sc[w * LK + k] - m);
            sc[w * LK + k] = e;
            s += e;
        }
#pragma unroll
        for (int o = 16; o; o >>= 1) s += __shfl_xor_sync(0xffffffffu, s, o);
        if (lane == 0) sinv[w] = 1.f / s;
    }
    __syncthreads();

    // ---- output: P @ V. thread -> (dim d, k-slice) ----
    {
        const int d = tid & 63;
        const int slice = tid >> 6;            // 0..3, 512 k each
        float acc[QT];
#pragma unroll
        for (int qi = 0; qi < QT; qi++) acc[qi] = 0.f;
        const int kbeg = slice * (LK / 4), kend = kbeg + (LK / 4);
#pragma unroll 4
        for (int k = kbeg; k < kend; k++) {
            float v = Vp[((size_t)(b * LK + k)) * DM + h * DK + d];
#pragma unroll
            for (int qi = 0; qi < QT; qi++) acc[qi] += sc[qi * LK + k] * v;
        }
#pragma unroll
        for (int qi = 0; qi < QT; qi++)
            outb[(slice * QT + qi) * DK + d] = acc[qi];
    }
    __syncthreads();

    // ---- reduce 4 slices, scale, store ----
    for (int i = tid; i < QT * DK; i += 256) {
        int qi = i >> 6, dd = i & 63;
        float r = outb[(0 * QT + qi) * DK + dd] + outb[(1 * QT + qi) * DK + dd] +
                  outb[(2 * QT + qi) * DK + dd] + outb[(3 * QT + qi) * DK + dd];
        Ao[((size_t)(b * LQ + q0 + qi)) * DM + h * DK + dd] = r * sinv[qi];
    }
}

// ---------------------------------------------------------------------------
extern "C" void kernel_launch(void* const* d_in, const int* in_sizes, int n_in,
                              void* d_out, int out_size)
{
    const float* q       = (const float*)d_in[0];
    const float* k       = (const float*)d_in[1];
    const float* v       = (const float*)d_in[2];
    const int*   b_idx   = (const int*)  d_in[3];
    const int*   mask    = (const int*)  d_in[4];
    const float* Wq      = (const float*)d_in[5];
    const float* bq      = (const float*)d_in[6];
    const float* Wk      = (const float*)d_in[7];
    const float* bk      = (const float*)d_in[8];
    const float* Wv      = (const float*)d_in[9];
    const float* bv      = (const float*)d_in[10];
    const float* Wo      = (const float*)d_in[11];
    const float* bo      = (const float*)d_in[12];
    const float* b_table = (const float*)d_in[13];
    float* out = (float*)d_out;

    void *Qp_, *Kp_, *Vp_, *Ao_;
    cudaGetSymbolAddress(&Qp_, g_Qp);
    cudaGetSymbolAddress(&Kp_, g_Kp);
    cudaGetSymbolAddress(&Vp_, g_Vp);
    cudaGetSymbolAddress(&Ao_, g_Ao);
    float* Qp = (float*)Qp_;
    float* Kp = (float*)Kp_;
    float* Vp = (float*)Vp_;
    float* Ao = (float*)Ao_;

    // projections
    sgemm_bt_kernel<<<dim3(DM / 128, (BSZ * LQ) / 128), 256>>>(q, Wq, bq, Qp, BSZ * LQ, DM, DM);
    sgemm_bt_kernel<<<dim3(DM / 128, (BSZ * LK) / 128), 256>>>(k, Wk, bk, Kp, BSZ * LK, DM, DM);
    sgemm_bt_kernel<<<dim3(DM / 128, (BSZ * LK) / 128), 256>>>(v, Wv, bv, Vp, BSZ * LK, DM, DM);

    // attention
    size_t shmem = (size_t)(QT * DK + VOCAB_B + QT * LK + 4 * QT * DK) * sizeof(float);
    cudaFuncSetAttribute(attn_kernel, cudaFuncAttributeMaxDynamicSharedMemorySize, (int)shmem);
    attn_kernel<<<dim3(NH, LQ / QT, BSZ), 256, shmem>>>(Qp, Kp, Vp, b_idx, mask, b_table, Ao);

    // output projection
    sgemm_bt_kernel<<<dim3(DM / 128, (BSZ * LQ) / 128), 256>>>(Ao, Wo, bo, out, BSZ * LQ, DM, DM);
}

// round 2
// speedup vs baseline: 2.1344x; 2.1344x over previous
#include <cuda_runtime.h>
#include <cstdint>

#define BSZ 4
#define LQ  512
#define LK  2048
#define DM  1024
#define NH  16
#define DK  64
#define VOCAB_B 900

// ---------------- scratch (static device memory; no runtime alloc) ----------
__device__ float g_Qp[BSZ * LQ * DM];            // projected Q
__device__ float g_Kp[BSZ * LK * DM];            // projected K
__device__ float g_Vp[BSZ * LK * DM];            // projected V
__device__ float g_Ao[BSZ * LQ * DM];            // attention output (concat heads)
__device__ float g_S [(size_t)BSZ * NH * LQ * LK]; // scores / probs (268MB)

// ---------------------------------------------------------------------------
// C[m][n] = sum_k A[m][k] * B[n][k] + bias[n]   (A @ B^T + bias)
// Tiles: 128x128x16, 256 threads, 8x8 per thread.
// ---------------------------------------------------------------------------
__global__ __launch_bounds__(256) void sgemm_bt_kernel(
    const float* __restrict__ A, const float* __restrict__ B,
    const float* __restrict__ bias, float* __restrict__ C,
    int M, int N, int K)
{
    const int BK = 16;
    __shared__ float As[BK][128];
    __shared__ float Bs[BK][128];

    const int tid = threadIdx.x;
    const int tx = tid & 15;
    const int ty = tid >> 4;
    const int m0 = blockIdx.y * 128;
    const int n0 = blockIdx.x * 128;

    float acc[8][8];
#pragma unroll
    for (int i = 0; i < 8; i++)
#pragma unroll
        for (int j = 0; j < 8; j++) acc[i][j] = 0.f;

    for (int k0 = 0; k0 < K; k0 += BK) {
#pragma unroll
        for (int t = 0; t < 2; t++) {
            int idx = tid + t * 256;
            int r   = idx >> 2;
            int c4  = (idx & 3) * 4;
            float4 a = *(const float4*)&A[(size_t)(m0 + r) * K + k0 + c4];
            As[c4 + 0][r] = a.x; As[c4 + 1][r] = a.y;
            As[c4 + 2][r] = a.z; As[c4 + 3][r] = a.w;
            float4 b = *(const float4*)&B[(size_t)(n0 + r) * K + k0 + c4];
            Bs[c4 + 0][r] = b.x; Bs[c4 + 1][r] = b.y;
            Bs[c4 + 2][r] = b.z; Bs[c4 + 3][r] = b.w;
        }
        __syncthreads();

#pragma unroll
        for (int kk = 0; kk < BK; kk++) {
            float ra[8], rb[8];
            *(float4*)&ra[0] = *(const float4*)&As[kk][ty * 8];
            *(float4*)&ra[4] = *(const float4*)&As[kk][ty * 8 + 4];
            *(float4*)&rb[0] = *(const float4*)&Bs[kk][tx * 8];
            *(float4*)&rb[4] = *(const float4*)&Bs[kk][tx * 8 + 4];
#pragma unroll
            for (int i = 0; i < 8; i++)
#pragma unroll
                for (int j = 0; j < 8; j++) acc[i][j] += ra[i] * rb[j];
        }
        __syncthreads();
    }

#pragma unroll
    for (int i = 0; i < 8; i++) {
        int m = m0 + ty * 8 + i;
#pragma unroll
        for (int j = 0; j < 8; j += 4) {
            int n = n0 + tx * 8 + j;
            float4 o;
            o.x = acc[i][j + 0] + bias[n + 0];
            o.y = acc[i][j + 1] + bias[n + 1];
            o.z = acc[i][j + 2] + bias[n + 2];
            o.w = acc[i][j + 3] + bias[n + 3];
            *(float4*)&C[(size_t)m * N + n] = o;
        }
    }
}

// ---------------------------------------------------------------------------
// S[bh][m][n] = (Q[m]·K[n]) / 8 + b_table[b_idx]  (or -1e9 where mask==0)
// Batched over bh = b*16+h. 128x128 tiles over (m=query, n=key), K-dim = 64.
// ---------------------------------------------------------------------------
__global__ __launch_bounds__(256) void qk_kernel(
    const float* __restrict__ Qp, const float* __restrict__ Kp,
    const int* __restrict__ b_idx, const int* __restrict__ mask,
    const float* __restrict__ b_table, float* __restrict__ S)
{
    const int bh = blockIdx.z;
    const int b  = bh >> 4;
    const int h  = bh & 15;
    const int m0 = blockIdx.y * 128;
    const int n0 = blockIdx.x * 128;

    __shared__ float As[16][128];
    __shared__ float Bs[16][128];
    __shared__ float bt[VOCAB_B];

    const int tid = threadIdx.x;
    const int tx = tid & 15;
    const int ty = tid >> 4;

    for (int i = tid; i < VOCAB_B; i += 256) bt[i] = b_table[i * NH + h];

    const float* A = Qp + (size_t)b * LQ * DM + h * DK;
    const float* B = Kp + (size_t)b * LK * DM + h * DK;

    float acc[8][8];
#pragma unroll
    for (int i = 0; i < 8; i++)
#pragma unroll
        for (int j = 0; j < 8; j++) acc[i][j] = 0.f;

#pragma unroll
    for (int k0 = 0; k0 < DK; k0 += 16) {
#pragma unroll
        for (int t = 0; t < 2; t++) {
            int idx = tid + t * 256;
            int r   = idx >> 2;
            int c4  = (idx & 3) * 4;
            float4 a = *(const float4*)&A[(size_t)(m0 + r) * DM + k0 + c4];
            As[c4 + 0][r] = a.x; As[c4 + 1][r] = a.y;
            As[c4 + 2][r] = a.z; As[c4 + 3][r] = a.w;
            float4 bb = *(const float4*)&B[(size_t)(n0 + r) * DM + k0 + c4];
            Bs[c4 + 0][r] = bb.x; Bs[c4 + 1][r] = bb.y;
            Bs[c4 + 2][r] = bb.z; Bs[c4 + 3][r] = bb.w;
        }
        __syncthreads();

#pragma unroll
        for (int kk = 0; kk < 16; kk++) {
            float ra[8], rb[8];
            *(float4*)&ra[0] = *(const float4*)&As[kk][ty * 8];
            *(float4*)&ra[4] = *(const float4*)&As[kk][ty * 8 + 4];
            *(float4*)&rb[0] = *(const float4*)&Bs[kk][tx * 8];
            *(float4*)&rb[4] = *(const float4*)&Bs[kk][tx * 8 + 4];
#pragma unroll
            for (int i = 0; i < 8; i++)
#pragma unroll
                for (int j = 0; j < 8; j++) acc[i][j] += ra[i] * rb[j];
        }
        __syncthreads();
    }

    // epilogue: scale + bias gather + mask, write scores
#pragma unroll
    for (int i = 0; i < 8; i++) {
        int m = m0 + ty * 8 + i;
        size_t gbase = ((size_t)(b * LQ + m)) * LK + n0 + tx * 8;
        int4 ix0 = *(const int4*)&b_idx[gbase];
        int4 ix1 = *(const int4*)&b_idx[gbase + 4];
        int4 mk0 = *(const int4*)&mask[gbase];
        int4 mk1 = *(const int4*)&mask[gbase + 4];
        float4 o0, o1;
        o0.x = mk0.x ? acc[i][0] * 0.125f + bt[ix0.x] : -1e9f;
        o0.y = mk0.y ? acc[i][1] * 0.125f + bt[ix0.y] : -1e9f;
        o0.z = mk0.z ? acc[i][2] * 0.125f + bt[ix0.z] : -1e9f;
        o0.w = mk0.w ? acc[i][3] * 0.125f + bt[ix0.w] : -1e9f;
        o1.x = mk1.x ? acc[i][4] * 0.125f + bt[ix1.x] : -1e9f;
        o1.y = mk1.y ? acc[i][5] * 0.125f + bt[ix1.y] : -1e9f;
        o1.z = mk1.z ? acc[i][6] * 0.125f + bt[ix1.z] : -1e9f;
        o1.w = mk1.w ? acc[i][7] * 0.125f + bt[ix1.w] : -1e9f;
        size_t sbase = ((size_t)bh * LQ + m) * LK + n0 + tx * 8;
        *(float4*)&S[sbase]     = o0;
        *(float4*)&S[sbase + 4] = o1;
    }
}

// ---------------------------------------------------------------------------
// Row softmax in place: one warp per row of 2048, fully register-resident.
// ---------------------------------------------------------------------------
__global__ __launch_bounds__(256) void softmax_kernel(float* __restrict__ S)
{
    const int row  = blockIdx.x * 8 + (threadIdx.x >> 5);
    const int lane = threadIdx.x & 31;
    float4* p = (float4*)(S + (size_t)row * LK);

    float4 v[16];
    float m = -3.4e38f;
#pragma unroll
    for (int i = 0; i < 16; i++) {
        v[i] = p[lane + i * 32];
        m = fmaxf(m, fmaxf(fmaxf(v[i].x, v[i].y), fmaxf(v[i].z, v[i].w)));
    }
#pragma unroll
    for (int o = 16; o; o >>= 1) m = fmaxf(m, __shfl_xor_sync(0xffffffffu, m, o));

    float s = 0.f;
#pragma unroll
    for (int i = 0; i < 16; i++) {
        v[i].x = __expf(v[i].x - m);
        v[i].y = __expf(v[i].y - m);
        v[i].z = __expf(v[i].z - m);
        v[i].w = __expf(v[i].w - m);
        s += v[i].x + v[i].y + v[i].z + v[i].w;
    }
#pragma unroll
    for (int o = 16; o; o >>= 1) s += __shfl_xor_sync(0xffffffffu, s, o);
    float inv = 1.f / s;

#pragma unroll
    for (int i = 0; i < 16; i++) {
        v[i].x *= inv; v[i].y *= inv; v[i].z *= inv; v[i].w *= inv;
        p[lane + i * 32] = v[i];
    }
}

// ---------------------------------------------------------------------------
// Ao[b, m, h*64+n] = sum_k P[bh][m][k] * Vp[b, k, h*64+n]
// Batched over bh. Tiles 64x64x16, 256 threads, 4x4 per thread.
// ---------------------------------------------------------------------------
__global__ __launch_bounds__(256) void pv_kernel(
    const float* __restrict__ S, const float* __restrict__ Vp,
    float* __restrict__ Ao)
{
    const int bh = blockIdx.z;
    const int b  = bh >> 4;
    const int h  = bh & 15;
    const int m0 = blockIdx.y * 64;

    const float* A = S  + (size_t)bh * LQ * LK;            // [LQ, LK]
    const float* B = Vp + (size_t)b * LK * DM + h * DK;    // rows k, stride DM

    __shared__ float As[16][64];
    __shared__ float Bs[16][64];

    const int tid = threadIdx.x;
    const int tx = tid & 15;
    const int ty = tid >> 4;
    const int ar  = tid >> 2;          // 0..63
    const int ac4 = (tid & 3) * 4;     // 0,4,8,12
    const int br  = tid >> 4;          // 0..15
    const int bc4 = (tid & 15) * 4;    // 0..60

    float acc[4][4];
#pragma unroll
    for (int i = 0; i < 4; i++)
#pragma unroll
        for (int j = 0; j < 4; j++) acc[i][j] = 0.f;

    for (int k0 = 0; k0 < LK; k0 += 16) {
        float4 a = *(const float4*)&A[(size_t)(m0 + ar) * LK + k0 + ac4];
        As[ac4 + 0][ar] = a.x; As[ac4 + 1][ar] = a.y;
        As[ac4 + 2][ar] = a.z; As[ac4 + 3][ar] = a.w;
        float4 bb = *(const float4*)&B[(size_t)(k0 + br) * DM + bc4];
        *(float4*)&Bs[br][bc4] = bb;
        __syncthreads();

#pragma unroll
        for (int kk = 0; kk < 16; kk++) {
            float ra[4], rb[4];
            *(float4*)&ra[0] = *(const float4*)&As[kk][ty * 4];
            *(float4*)&rb[0] = *(const float4*)&Bs[kk][tx * 4];
#pragma unroll
            for (int i = 0; i < 4; i++)
#pragma unroll
                for (int j = 0; j < 4; j++) acc[i][j] += ra[i] * rb[j];
        }
        __syncthreads();
    }

#pragma unroll
    for (int i = 0; i < 4; i++) {
        int m = m0 + ty * 4 + i;
        float4 o;
        o.x = acc[i][0]; o.y = acc[i][1]; o.z = acc[i][2]; o.w = acc[i][3];
        *(float4*)&Ao[((size_t)(b * LQ + m)) * DM + h * DK + tx * 4] = o;
    }
}

// ---------------------------------------------------------------------------
extern "C" void kernel_launch(void* const* d_in, const int* in_sizes, int n_in,
                              void* d_out, int out_size)
{
    const float* q       = (const float*)d_in[0];
    const float* k       = (const float*)d_in[1];
    const float* v       = (const float*)d_in[2];
    const int*   b_idx   = (const int*)  d_in[3];
    const int*   mask    = (const int*)  d_in[4];
    const float* Wq      = (const float*)d_in[5];
    const float* bq      = (const float*)d_in[6];
    const float* Wk      = (const float*)d_in[7];
    const float* bk      = (const float*)d_in[8];
    const float* Wv      = (const float*)d_in[9];
    const float* bv      = (const float*)d_in[10];
    const float* Wo      = (const float*)d_in[11];
    const float* bo      = (const float*)d_in[12];
    const float* b_table = (const float*)d_in[13];
    float* out = (float*)d_out;

    void *Qp_, *Kp_, *Vp_, *Ao_, *S_;
    cudaGetSymbolAddress(&Qp_, g_Qp);
    cudaGetSymbolAddress(&Kp_, g_Kp);
    cudaGetSymbolAddress(&Vp_, g_Vp);
    cudaGetSymbolAddress(&Ao_, g_Ao);
    cudaGetSymbolAddress(&S_,  g_S);
    float* Qp = (float*)Qp_;
    float* Kp = (float*)Kp_;
    float* Vp = (float*)Vp_;
    float* Ao = (float*)Ao_;
    float* S  = (float*)S_;

    // projections
    sgemm_bt_kernel<<<dim3(DM / 128, (BSZ * LQ) / 128), 256>>>(q, Wq, bq, Qp, BSZ * LQ, DM, DM);
    sgemm_bt_kernel<<<dim3(DM / 128, (BSZ * LK) / 128), 256>>>(k, Wk, bk, Kp, BSZ * LK, DM, DM);
    sgemm_bt_kernel<<<dim3(DM / 128, (BSZ * LK) / 128), 256>>>(v, Wv, bv, Vp, BSZ * LK, DM, DM);

    // attention as batched GEMMs
    qk_kernel<<<dim3(LK / 128, LQ / 128, BSZ * NH), 256>>>(Qp, Kp, b_idx, mask, b_table, S);
    softmax_kernel<<<(BSZ * NH * LQ) / 8, 256>>>(S);
    pv_kernel<<<dim3(1, LQ / 64, BSZ * NH), 256>>>(S, Vp, Ao);

    // output projection
    sgemm_bt_kernel<<<dim3(DM / 128, (BSZ * LQ) / 128), 256>>>(Ao, Wo, bo, out, BSZ * LQ, DM, DM);
}

// round 3
// speedup vs baseline: 6.3013x; 2.9523x over previous
#include <cuda_runtime.h>
#include <cstdint>

#define BSZ 4
#define LQ  512
#define LK  2048
#define DM  1024
#define NH  16
#define DK  64
#define VOCAB_B 900

// ---------------- scratch (static device memory; no runtime alloc) ----------
__device__ float g_Qp[BSZ * LQ * DM];
__device__ float g_Kp[BSZ * LK * DM];
__device__ float g_Vp[BSZ * LK * DM];
__device__ float g_Vt[BSZ * DM * LK];            // V transposed: [b][dm][k]
__device__ float g_Ao[BSZ * LQ * DM];
__device__ float g_S [(size_t)BSZ * NH * LQ * LK];

// ---------------- PTX helpers ----------------------------------------------
__device__ __forceinline__ uint32_t s_u32(const void* p) {
    uint32_t a;
    asm("{.reg .u64 t; cvta.to.shared.u64 t, %1; cvt.u32.u64 %0, t;}"
        : "=r"(a) : "l"(p));
    return a;
}

#define LDSM4(R0,R1,R2,R3,ADDR) \
    asm volatile("ldmatrix.sync.aligned.m8n8.x4.shared.b16 {%0,%1,%2,%3},[%4];" \
        : "=r"(R0),"=r"(R1),"=r"(R2),"=r"(R3) : "r"(ADDR))

#define CVT_TF32(T) asm volatile("cvt.rna.tf32.f32 %0,%0;" : "+r"(T))

#define MMA_TF32(D,A,B0,B1) \
    asm volatile("mma.sync.aligned.m16n8k8.row.col.f32.tf32.tf32.f32 " \
        "{%0,%1,%2,%3},{%4,%5,%6,%7},{%8,%9},{%0,%1,%2,%3};" \
        : "+f"(D[0]),"+f"(D[1]),"+f"(D[2]),"+f"(D[3]) \
        : "r"(A[0]),"r"(A[1]),"r"(A[2]),"r"(A[3]),"r"(B0),"r"(B1))

#define CP16(DST,SRC) \
    asm volatile("cp.async.cg.shared.global [%0],[%1],16;" :: "r"(DST),"l"(SRC))
#define CPCOMMIT  asm volatile("cp.async.commit_group;")
#define CPWAIT0   asm volatile("cp.async.wait_group 0;")
#define CPWAIT1   asm volatile("cp.async.wait_group 1;")

// ============================================================================
// tf32 GEMM: C[M,N] = A[M,K] @ B[N,K]^T + bias[n]
// CTA 128x128, BK=32, 8 warps (2m x 4n), warp tile 64x32.
// Smem: [buf][A 128x32][B 128x32], 16B-granule XOR swizzle, ldmatrix frags.
// ============================================================================
__global__ __launch_bounds__(256, 2) void gemm_bt_tf32(
    const float* __restrict__ A, const float* __restrict__ B,
    const float* __restrict__ bias, float* __restrict__ C,
    int M, int N, int K)
{
    extern __shared__ float smem[];
    const uint32_t sbase = s_u32(smem);
    const int tid = threadIdx.x;
    const int m0 = blockIdx.y * 128, n0 = blockIdx.x * 128;
    const int l  = tid & 31, w = tid >> 5;
    const int mw = (w >> 2) * 64, nw = (w & 3) * 32;
    const int lrow = l & 15, lq = l >> 4, lx = l & 7;
    const int sm = tid >> 3, sg = tid & 7;     // staging row / granule

    float acc[4][4][4];
#pragma unroll
    for (int i = 0; i < 4; i++)
#pragma unroll
        for (int j = 0; j < 4; j++)
#pragma unroll
            for (int r = 0; r < 4; r++) acc[i][j][r] = 0.f;

    const int NIT = K >> 5;

#define STAGE_G(IT, BUF) do {                                                  \
    uint32_t sA_ = sbase + (BUF) * 32768;                                      \
    uint32_t sB_ = sA_ + 16384;                                                \
    const float* Ag_ = A + (size_t)(m0) * K + (IT) * 32;                       \
    const float* Bg_ = B + (size_t)(n0) * K + (IT) * 32;                       \
    _Pragma("unroll")                                                          \
    for (int i_ = 0; i_ < 4; i_++) {                                           \
        int r_ = sm + i_ * 32;                                                 \
        CP16(sA_ + r_ * 128 + (((sg ^ (r_ & 7)) << 4)),                        \
             Ag_ + (size_t)r_ * K + sg * 4);                                   \
    }                                                                          \
    _Pragma("unroll")                                                          \
    for (int i_ = 0; i_ < 4; i_++) {                                           \
        int r_ = sm + i_ * 32;                                                 \
        CP16(sB_ + r_ * 128 + (((sg ^ (r_ & 7)) << 4)),                        \
             Bg_ + (size_t)r_ * K + sg * 4);                                   \
    }                                                                          \
} while (0)

    STAGE_G(0, 0);
    CPCOMMIT;

    int buf = 0;
    for (int it = 0; it < NIT; ++it) {
        if (it + 1 < NIT) { STAGE_G(it + 1, buf ^ 1); CPCOMMIT; CPWAIT1; }
        else              { CPWAIT0; }
        __syncthreads();

        const uint32_t sA = sbase + buf * 32768;
        const uint32_t sB = sA + 16384;
        const uint32_t aAdr0 = sA + (mw + lrow) * 128;
        const uint32_t bAdr0 = sB + (nw + (l & 7)) * 128;

#pragma unroll
        for (int s = 0; s < 4; s += 2) {
            uint32_t b[4][4];
#pragma unroll
            for (int nf = 0; nf < 4; nf++) {
                uint32_t ad = bAdr0 + nf * 1024 +
                              (((2 * s + ((l >> 3) & 3)) ^ lx) << 4);
                LDSM4(b[nf][0], b[nf][1], b[nf][2], b[nf][3], ad);
                CVT_TF32(b[nf][0]); CVT_TF32(b[nf][1]);
                CVT_TF32(b[nf][2]); CVT_TF32(b[nf][3]);
            }
#pragma unroll
            for (int ss = 0; ss < 2; ss++) {
                uint32_t a[4][4];
#pragma unroll
                for (int mf = 0; mf < 4; mf++) {
                    uint32_t ad = aAdr0 + mf * 2048 +
                                  (((2 * (s + ss) + lq) ^ lx) << 4);
                    LDSM4(a[mf][0], a[mf][1], a[mf][2], a[mf][3], ad);
                    CVT_TF32(a[mf][0]); CVT_TF32(a[mf][1]);
                    CVT_TF32(a[mf][2]); CVT_TF32(a[mf][3]);
                }
#pragma unroll
                for (int mf = 0; mf < 4; mf++)
#pragma unroll
                    for (int nf = 0; nf < 4; nf++)
                        MMA_TF32(acc[mf][nf], a[mf], b[nf][2 * ss], b[nf][2 * ss + 1]);
            }
        }
        __syncthreads();
        buf ^= 1;
    }
#undef STAGE_G

    // epilogue: + bias, float2 stores
#pragma unroll
    for (int mf = 0; mf < 4; mf++) {
        int row = m0 + mw + mf * 16 + (l >> 2);
#pragma unroll
        for (int nf = 0; nf < 4; nf++) {
            int col = n0 + nw + nf * 8 + (l & 3) * 2;
            float2 bb = *(const float2*)&bias[col];
            float2 o0, o1;
            o0.x = acc[mf][nf][0] + bb.x; o0.y = acc[mf][nf][1] + bb.y;
            o1.x = acc[mf][nf][2] + bb.x; o1.y = acc[mf][nf][3] + bb.y;
            *(float2*)&C[(size_t)row * N + col]       = o0;
            *(float2*)&C[(size_t)(row + 8) * N + col] = o1;
        }
    }
}

// ============================================================================
// qk: S[bh][m][n] = (Q[m]·K[n])/8 + b_table[b_idx]  (or -1e9 where mask==0)
// CTA 128x128, K=64 (2 BK iters). blockIdx: x=n tile, y=m tile, z=bh.
// ============================================================================
__global__ __launch_bounds__(256, 2) void qk_tf32(
    const float* __restrict__ Qp, const float* __restrict__ Kp,
    const int* __restrict__ b_idx, const int* __restrict__ mask,
    const float* __restrict__ b_table, float* __restrict__ S)
{
    extern __shared__ float smem[];
    const uint32_t sbase = s_u32(smem);
    float* btm = smem + 16384;
    const int tid = threadIdx.x;
    const int bh = blockIdx.z, b = bh >> 4, h = bh & 15;
    const int m0 = blockIdx.y * 128, n0 = blockIdx.x * 128;
    const int l  = tid & 31, w = tid >> 5;
    const int mw = (w >> 2) * 64, nw = (w & 3) * 32;
    const int lrow = l & 15, lq = l >> 4, lx = l & 7;
    const int sm = tid >> 3, sg = tid & 7;

    for (int i = tid; i < VOCAB_B; i += 256) btm[i] = b_table[i * NH + h];

    const float* Ag0 = Qp + (size_t)(b * LQ + m0) * DM + h * DK;
    const float* Bg0 = Kp + (size_t)(b * LK + n0) * DM + h * DK;

    float acc[4][4][4];
#pragma unroll
    for (int i = 0; i < 4; i++)
#pragma unroll
        for (int j = 0; j < 4; j++)
#pragma unroll
            for (int r = 0; r < 4; r++) acc[i][j][r] = 0.f;

#define STAGE_QK(IT, BUF) do {                                                 \
    uint32_t sA_ = sbase + (BUF) * 32768;                                      \
    uint32_t sB_ = sA_ + 16384;                                                \
    const float* Ag_ = Ag0 + (IT) * 32;                                        \
    const float* Bg_ = Bg0 + (IT) * 32;                                        \
    _Pragma("unroll")                                                          \
    for (int i_ = 0; i_ < 4; i_++) {                                           \
        int r_ = sm + i_ * 32;                                                 \
        CP16(sA_ + r_ * 128 + (((sg ^ (r_ & 7)) << 4)),                        \
             Ag_ + (size_t)r_ * DM + sg * 4);                                  \
    }                                                                          \
    _Pragma("unroll")                                                          \
    for (int i_ = 0; i_ < 4; i_++) {                                           \
        int r_ = sm + i_ * 32;                                                 \
        CP16(sB_ + r_ * 128 + (((sg ^ (r_ & 7)) << 4)),                        \
             Bg_ + (size_t)r_ * DM + sg * 4);                                  \
    }                                                                          \
} while (0)

    STAGE_QK(0, 0);
    CPCOMMIT;

    int buf = 0;
#pragma unroll
    for (int it = 0; it < 2; ++it) {
        if (it == 0) { STAGE_QK(1, 1); CPCOMMIT; CPWAIT1; }
        else         { CPWAIT0; }
        __syncthreads();

        const uint32_t sA = sbase + buf * 32768;
        const uint32_t sB = sA + 16384;
        const uint32_t aAdr0 = sA + (mw + lrow) * 128;
        const uint32_t bAdr0 = sB + (nw + (l & 7)) * 128;

#pragma unroll
        for (int s = 0; s < 4; s += 2) {
            uint32_t bfr[4][4];
#pragma unroll
            for (int nf = 0; nf < 4; nf++) {
                uint32_t ad = bAdr0 + nf * 1024 +
                              (((2 * s + ((l >> 3) & 3)) ^ lx) << 4);
                LDSM4(bfr[nf][0], bfr[nf][1], bfr[nf][2], bfr[nf][3], ad);
                CVT_TF32(bfr[nf][0]); CVT_TF32(bfr[nf][1]);
                CVT_TF32(bfr[nf][2]); CVT_TF32(bfr[nf][3]);
            }
#pragma unroll
            for (int ss = 0; ss < 2; ss++) {
                uint32_t a[4][4];
#pragma unroll
                for (int mf = 0; mf < 4; mf++) {
                    uint32_t ad = aAdr0 + mf * 2048 +
                                  (((2 * (s + ss) + lq) ^ lx) << 4);
                    LDSM4(a[mf][0], a[mf][1], a[mf][2], a[mf][3], ad);
                    CVT_TF32(a[mf][0]); CVT_TF32(a[mf][1]);
                    CVT_TF32(a[mf][2]); CVT_TF32(a[mf][3]);
                }
#pragma unroll
                for (int mf = 0; mf < 4; mf++)
#pragma unroll
                    for (int nf = 0; nf < 4; nf++)
                        MMA_TF32(acc[mf][nf], a[mf], bfr[nf][2 * ss], bfr[nf][2 * ss + 1]);
            }
        }
        __syncthreads();
        buf ^= 1;
    }
#undef STAGE_QK

    // epilogue: scale, bias gather, mask
#pragma unroll
    for (int mf = 0; mf < 4; mf++) {
        int row = m0 + mw + mf * 16 + (l >> 2);
#pragma unroll
        for (int nf = 0; nf < 4; nf++) {
            int col = n0 + nw + nf * 8 + (l & 3) * 2;
#pragma unroll
            for (int rr = 0; rr < 2; rr++) {
                int r = row + rr * 8;
                size_t gm = ((size_t)(b * LQ + r)) * LK + col;
                int2 ix = *(const int2*)&b_idx[gm];
                int2 mk = *(const int2*)&mask[gm];
                float2 o;
                o.x = mk.x ? acc[mf][nf][rr * 2 + 0] * 0.125f + btm[ix.x] : -1e9f;
                o.y = mk.y ? acc[mf][nf][rr * 2 + 1] * 0.125f + btm[ix.y] : -1e9f;
                *(float2*)&S[((size_t)bh * LQ + r) * LK + col] = o;
            }
        }
    }
}

// ============================================================================
// Row softmax in place: one warp per row of 2048, register-resident.
// ============================================================================
__global__ __launch_bounds__(256) void softmax_kernel(float* __restrict__ S)
{
    const int row  = blockIdx.x * 8 + (threadIdx.x >> 5);
    const int lane = threadIdx.x & 31;
    float4* p = (float4*)(S + (size_t)row * LK);

    float4 v[16];
    float m = -3.4e38f;
#pragma unroll
    for (int i = 0; i < 16; i++) {
        v[i] = p[lane + i * 32];
        m = fmaxf(m, fmaxf(fmaxf(v[i].x, v[i].y), fmaxf(v[i].z, v[i].w)));
    }
#pragma unroll
    for (int o = 16; o; o >>= 1) m = fmaxf(m, __shfl_xor_sync(0xffffffffu, m, o));

    float s = 0.f;
#pragma unroll
    for (int i = 0; i < 16; i++) {
        v[i].x = __expf(v[i].x - m); v[i].y = __expf(v[i].y - m);
        v[i].z = __expf(v[i].z - m); v[i].w = __expf(v[i].w - m);
        s += v[i].x + v[i].y + v[i].z + v[i].w;
    }
#pragma unroll
    for (int o = 16; o; o >>= 1) s += __shfl_xor_sync(0xffffffffu, s, o);
    float inv = 1.f / s;

#pragma unroll
    for (int i = 0; i < 16; i++) {
        v[i].x *= inv; v[i].y *= inv; v[i].z *= inv; v[i].w *= inv;
        p[lane + i * 32] = v[i];
    }
}

// ============================================================================
// V transpose: Vt[b][d][k] = Vp[b*LK + k][d]
// ============================================================================
__global__ __launch_bounds__(256) void vtrans_kernel(
    const float* __restrict__ Vp, float* __restrict__ Vt)
{
    __shared__ float tl[32][33];
    const int k0 = blockIdx.x * 32, d0 = blockIdx.y * 32, b = blockIdx.z;
    const int tx = threadIdx.x & 31, ty = threadIdx.x >> 5;
#pragma unroll
    for (int i = 0; i < 4; i++)
        tl[ty + i * 8][tx] = Vp[((size_t)(b * LK + k0 + ty + i * 8)) * DM + d0 + tx];
    __syncthreads();
#pragma unroll
    for (int i = 0; i < 4; i++)
        Vt[((size_t)(b * DM + d0 + ty + i * 8)) * LK + k0 + tx] = tl[tx][ty + i * 8];
}

// ============================================================================
// pv: Ao[b,m,h*64+n] = sum_k P[bh][m][k] * Vt[b][h*64+n][k]
// CTA 128m x 64n, BK=32, 8 warps (4m x 2n), warp tile 32x32.
// blockIdx: x = m tile (4), y = bh (64).
// ============================================================================
__global__ __launch_bounds__(256, 2) void pv_tf32(
    const float* __restrict__ S, const float* __restrict__ Vt,
    float* __restrict__ Ao)
{
    extern __shared__ float smem[];
    const uint32_t sbase = s_u32(smem);
    const int tid = threadIdx.x;
    const int bh = blockIdx.y, b = bh >> 4, h = bh & 15;
    const int m0 = blockIdx.x * 128;
    const int l  = tid & 31, w = tid >> 5;
    const int mw = (w >> 1) * 32, nw = (w & 1) * 32;
    const int lrow = l & 15, lq = l >> 4, lx = l & 7;
    const int sm = tid >> 3, sg = tid & 7;

    const float* Ag0 = S  + ((size_t)bh * LQ + m0) * LK;
    const float* Bg0 = Vt + ((size_t)(b * DM + h * DK)) * LK;

    float acc[2][4][4];
#pragma unroll
    for (int i = 0; i < 2; i++)
#pragma unroll
        for (int j = 0; j < 4; j++)
#pragma unroll
            for (int r = 0; r < 4; r++) acc[i][j][r] = 0.f;

#define STAGE_PV(IT, BUF) do {                                                 \
    uint32_t sA_ = sbase + (BUF) * 24576;                                      \
    uint32_t sB_ = sA_ + 16384;                                                \
    const float* Ag_ = Ag0 + (IT) * 32;                                        \
    const float* Bg_ = Bg0 + (IT) * 32;                                        \
    _Pragma("unroll")                                                          \
    for (int i_ = 0; i_ < 4; i_++) {                                           \
        int r_ = sm + i_ * 32;                                                 \
        CP16(sA_ + r_ * 128 + (((sg ^ (r_ & 7)) << 4)),                        \
             Ag_ + (size_t)r_ * LK + sg * 4);                                  \
    }                                                                          \
    _Pragma("unroll")                                                          \
    for (int i_ = 0; i_ < 2; i_++) {                                           \
        int r_ = sm + i_ * 32;                                                 \
        CP16(sB_ + r_ * 128 + (((sg ^ (r_ & 7)) << 4)),                        \
             Bg_ + (size_t)r_ * LK + sg * 4);                                  \
    }                                                                          \
} while (0)

    STAGE_PV(0, 0);
    CPCOMMIT;

    int buf = 0;
    const int NIT = LK / 32;   // 64
    for (int it = 0; it < NIT; ++it) {
        if (it + 1 < NIT) { STAGE_PV(it + 1, buf ^ 1); CPCOMMIT; CPWAIT1; }
        else              { CPWAIT0; }
        __syncthreads();

        const uint32_t sA = sbase + buf * 24576;
        const uint32_t sB = sA + 16384;
        const uint32_t aAdr0 = sA + (mw + lrow) * 128;
        const uint32_t bAdr0 = sB + (nw + (l & 7)) * 128;

#pragma unroll
        for (int s = 0; s < 4; s += 2) {
            uint32_t bfr[4][4];
#pragma unroll
            for (int nf = 0; nf < 4; nf++) {
                uint32_t ad = bAdr0 + nf * 1024 +
                              (((2 * s + ((l >> 3) & 3)) ^ lx) << 4);
                LDSM4(bfr[nf][0], bfr[nf][1], bfr[nf][2], bfr[nf][3], ad);
                CVT_TF32(bfr[nf][0]); CVT_TF32(bfr[nf][1]);
                CVT_TF32(bfr[nf][2]); CVT_TF32(bfr[nf][3]);
            }
#pragma unroll
            for (int ss = 0; ss < 2; ss++) {
                uint32_t a[2][4];
#pragma unroll
                for (int mf = 0; mf < 2; mf++) {
                    uint32_t ad = aAdr0 + mf * 2048 +
                                  (((2 * (s + ss) + lq) ^ lx) << 4);
                    LDSM4(a[mf][0], a[mf][1], a[mf][2], a[mf][3], ad);
                    CVT_TF32(a[mf][0]); CVT_TF32(a[mf][1]);
                    CVT_TF32(a[mf][2]); CVT_TF32(a[mf][3]);
                }
#pragma unroll
                for (int mf = 0; mf < 2; mf++)
#pragma unroll
                    for (int nf = 0; nf < 4; nf++)
                        MMA_TF32(acc[mf][nf], a[mf], bfr[nf][2 * ss], bfr[nf][2 * ss + 1]);
            }
        }
        __syncthreads();
        buf ^= 1;
    }
#undef STAGE_PV

#pragma unroll
    for (int mf = 0; mf < 2; mf++) {
        int row = m0 + mw + mf * 16 + (l >> 2);
#pragma unroll
        for (int nf = 0; nf < 4; nf++) {
            int col = h * DK + nw + nf * 8 + (l & 3) * 2;
            float2 o0, o1;
            o0.x = acc[mf][nf][0]; o0.y = acc[mf][nf][1];
            o1.x = acc[mf][nf][2]; o1.y = acc[mf][nf][3];
            *(float2*)&Ao[((size_t)(b * LQ + row)) * DM + col]       = o0;
            *(float2*)&Ao[((size_t)(b * LQ + row + 8)) * DM + col]   = o1;
        }
    }
}

// ---------------------------------------------------------------------------
extern "C" void kernel_launch(void* const* d_in, const int* in_sizes, int n_in,
                              void* d_out, int out_size)
{
    const float* q       = (const float*)d_in[0];
    const float* k       = (const float*)d_in[1];
    const float* v       = (const float*)d_in[2];
    const int*   b_idx   = (const int*)  d_in[3];
    const int*   mask    = (const int*)  d_in[4];
    const float* Wq      = (const float*)d_in[5];
    const float* bq      = (const float*)d_in[6];
    const float* Wk      = (const float*)d_in[7];
    const float* bk      = (const float*)d_in[8];
    const float* Wv      = (const float*)d_in[9];
    const float* bv      = (const float*)d_in[10];
    const float* Wo      = (const float*)d_in[11];
    const float* bo      = (const float*)d_in[12];
    const float* b_table = (const float*)d_in[13];
    float* out = (float*)d_out;

    void *Qp_, *Kp_, *Vp_, *Vt_, *Ao_, *S_;
    cudaGetSymbolAddress(&Qp_, g_Qp);
    cudaGetSymbolAddress(&Kp_, g_Kp);
    cudaGetSymbolAddress(&Vp_, g_Vp);
    cudaGetSymbolAddress(&Vt_, g_Vt);
    cudaGetSymbolAddress(&Ao_, g_Ao);
    cudaGetSymbolAddress(&S_,  g_S);
    float* Qp = (float*)Qp_;
    float* Kp = (float*)Kp_;
    float* Vp = (float*)Vp_;
    float* Vt = (float*)Vt_;
    float* Ao = (float*)Ao_;
    float* S  = (float*)S_;

    static int attr_set = 0;
    if (!attr_set) {
        cudaFuncSetAttribute(gemm_bt_tf32, cudaFuncAttributeMaxDynamicSharedMemorySize, 65536);
        cudaFuncSetAttribute(qk_tf32,      cudaFuncAttributeMaxDynamicSharedMemorySize, 69632);
        cudaFuncSetAttribute(pv_tf32,      cudaFuncAttributeMaxDynamicSharedMemorySize, 49152);
        attr_set = 1;
    }

    // projections
    gemm_bt_tf32<<<dim3(DM / 128, (BSZ * LQ) / 128), 256, 65536>>>(q, Wq, bq, Qp, BSZ * LQ, DM, DM);
    gemm_bt_tf32<<<dim3(DM / 128, (BSZ * LK) / 128), 256, 65536>>>(k, Wk, bk, Kp, BSZ * LK, DM, DM);
    gemm_bt_tf32<<<dim3(DM / 128, (BSZ * LK) / 128), 256, 65536>>>(v, Wv, bv, Vp, BSZ * LK, DM, DM);
    vtrans_kernel<<<dim3(LK / 32, DM / 32, BSZ), 256>>>(Vp, Vt);

    // attention
    qk_tf32<<<dim3(LK / 128, LQ / 128, BSZ * NH), 256, 69632>>>(Qp, Kp, b_idx, mask, b_table, S);
    softmax_kernel<<<(BSZ * NH * LQ) / 8, 256>>>(S);
    pv_tf32<<<dim3(LQ / 128, BSZ * NH), 256, 49152>>>(S, Vt, Ao);

    // output projection
    gemm_bt_tf32<<<dim3(DM / 128, (BSZ * LQ) / 128), 256, 65536>>>(Ao, Wo, bo, out, BSZ * LQ, DM, DM);
}

// round 4
// speedup vs baseline: 6.7812x; 1.0762x over previous
#include <cuda_runtime.h>
#include <cstdint>
#include <math_constants.h>

#define BSZ 4
#define LQ  512
#define LK  2048
#define DM  1024
#define NH  16
#define DK  64
#define VOCAB_B 900

// ---------------- scratch (static device memory; no runtime alloc) ----------
__device__ float g_Qp[BSZ * LQ * DM];
__device__ float g_Kp[BSZ * LK * DM];
__device__ float g_Vp[BSZ * LK * DM];
__device__ float g_Vt[BSZ * DM * LK];            // V transposed: [b][dm][k]
__device__ float g_Ao[BSZ * LQ * DM];

// ---------------- PTX helpers ----------------------------------------------
__device__ __forceinline__ uint32_t s_u32(const void* p) {
    uint32_t a;
    asm("{.reg .u64 t; cvta.to.shared.u64 t, %1; cvt.u32.u64 %0, t;}"
        : "=r"(a) : "l"(p));
    return a;
}

#define LDSM4(R0,R1,R2,R3,ADDR) \
    asm volatile("ldmatrix.sync.aligned.m8n8.x4.shared.b16 {%0,%1,%2,%3},[%4];" \
        : "=r"(R0),"=r"(R1),"=r"(R2),"=r"(R3) : "r"(ADDR))

#define CVT_TF32(T) asm volatile("cvt.rna.tf32.f32 %0,%0;" : "+r"(T))

#define MMA_TF32(D,A,B0,B1) \
    asm volatile("mma.sync.aligned.m16n8k8.row.col.f32.tf32.tf32.f32 " \
        "{%0,%1,%2,%3},{%4,%5,%6,%7},{%8,%9},{%0,%1,%2,%3};" \
        : "+f"(D[0]),"+f"(D[1]),"+f"(D[2]),"+f"(D[3]) \
        : "r"(A[0]),"r"(A[1]),"r"(A[2]),"r"(A[3]),"r"(B0),"r"(B1))

#define CP16(DST,SRC) \
    asm volatile("cp.async.cg.shared.global [%0],[%1],16;" :: "r"(DST),"l"(SRC))
#define CPCOMMIT  asm volatile("cp.async.commit_group;")
#define CPWAIT0   asm volatile("cp.async.wait_group 0;")
#define CPWAIT1   asm volatile("cp.async.wait_group 1;")

// ============================================================================
// tf32 GEMM: C[M,N] = A[M,K] @ B[N,K]^T + bias[n]   (unchanged, known good)
// ============================================================================
__global__ __launch_bounds__(256, 2) void gemm_bt_tf32(
    const float* __restrict__ A, const float* __restrict__ B,
    const float* __restrict__ bias, float* __restrict__ C,
    int M, int N, int K)
{
    extern __shared__ float smem[];
    const uint32_t sbase = s_u32(smem);
    const int tid = threadIdx.x;
    const int m0 = blockIdx.y * 128, n0 = blockIdx.x * 128;
    const int l  = tid & 31, w = tid >> 5;
    const int mw = (w >> 2) * 64, nw = (w & 3) * 32;
    const int lrow = l & 15, lq = l >> 4, lx = l & 7;
    const int sm = tid >> 3, sg = tid & 7;

    float acc[4][4][4];
#pragma unroll
    for (int i = 0; i < 4; i++)
#pragma unroll
        for (int j = 0; j < 4; j++)
#pragma unroll
            for (int r = 0; r < 4; r++) acc[i][j][r] = 0.f;

    const int NIT = K >> 5;

#define STAGE_G(IT, BUF) do {                                                  \
    uint32_t sA_ = sbase + (BUF) * 32768;                                      \
    uint32_t sB_ = sA_ + 16384;                                                \
    const float* Ag_ = A + (size_t)(m0) * K + (IT) * 32;                       \
    const float* Bg_ = B + (size_t)(n0) * K + (IT) * 32;                       \
    _Pragma("unroll")                                                          \
    for (int i_ = 0; i_ < 4; i_++) {                                           \
        int r_ = sm + i_ * 32;                                                 \
        CP16(sA_ + r_ * 128 + (((sg ^ (r_ & 7)) << 4)),                        \
             Ag_ + (size_t)r_ * K + sg * 4);                                   \
    }                                                                          \
    _Pragma("unroll")                                                          \
    for (int i_ = 0; i_ < 4; i_++) {                                           \
        int r_ = sm + i_ * 32;                                                 \
        CP16(sB_ + r_ * 128 + (((sg ^ (r_ & 7)) << 4)),                        \
             Bg_ + (size_t)r_ * K + sg * 4);                                   \
    }                                                                          \
} while (0)

    STAGE_G(0, 0);
    CPCOMMIT;

    int buf = 0;
    for (int it = 0; it < NIT; ++it) {
        if (it + 1 < NIT) { STAGE_G(it + 1, buf ^ 1); CPCOMMIT; CPWAIT1; }
        else              { CPWAIT0; }
        __syncthreads();

        const uint32_t sA = sbase + buf * 32768;
        const uint32_t sB = sA + 16384;
        const uint32_t aAdr0 = sA + (mw + lrow) * 128;
        const uint32_t bAdr0 = sB + (nw + (l & 7)) * 128;

#pragma unroll
        for (int s = 0; s < 4; s += 2) {
            uint32_t b[4][4];
#pragma unroll
            for (int nf = 0; nf < 4; nf++) {
                uint32_t ad = bAdr0 + nf * 1024 +
                              (((2 * s + ((l >> 3) & 3)) ^ lx) << 4);
                LDSM4(b[nf][0], b[nf][1], b[nf][2], b[nf][3], ad);
                CVT_TF32(b[nf][0]); CVT_TF32(b[nf][1]);
                CVT_TF32(b[nf][2]); CVT_TF32(b[nf][3]);
            }
#pragma unroll
            for (int ss = 0; ss < 2; ss++) {
                uint32_t a[4][4];
#pragma unroll
                for (int mf = 0; mf < 4; mf++) {
                    uint32_t ad = aAdr0 + mf * 2048 +
                                  (((2 * (s + ss) + lq) ^ lx) << 4);
                    LDSM4(a[mf][0], a[mf][1], a[mf][2], a[mf][3], ad);
                    CVT_TF32(a[mf][0]); CVT_TF32(a[mf][1]);
                    CVT_TF32(a[mf][2]); CVT_TF32(a[mf][3]);
                }
#pragma unroll
                for (int mf = 0; mf < 4; mf++)
#pragma unroll
                    for (int nf = 0; nf < 4; nf++)
                        MMA_TF32(acc[mf][nf], a[mf], b[nf][2 * ss], b[nf][2 * ss + 1]);
            }
        }
        __syncthreads();
        buf ^= 1;
    }
#undef STAGE_G

#pragma unroll
    for (int mf = 0; mf < 4; mf++) {
        int row = m0 + mw + mf * 16 + (l >> 2);
#pragma unroll
        for (int nf = 0; nf < 4; nf++) {
            int col = n0 + nw + nf * 8 + (l & 3) * 2;
            float2 bb = *(const float2*)&bias[col];
            float2 o0, o1;
            o0.x = acc[mf][nf][0] + bb.x; o0.y = acc[mf][nf][1] + bb.y;
            o1.x = acc[mf][nf][2] + bb.x; o1.y = acc[mf][nf][3] + bb.y;
            *(float2*)&C[(size_t)row * N + col]       = o0;
            *(float2*)&C[(size_t)(row + 8) * N + col] = o1;
        }
    }
}

// ============================================================================
// V transpose: Vt[b][d][k] = Vp[b*LK + k][d]
// ============================================================================
__global__ __launch_bounds__(256) void vtrans_kernel(
    const float* __restrict__ Vp, float* __restrict__ Vt)
{
    __shared__ float tl[32][33];
    const int k0 = blockIdx.x * 32, d0 = blockIdx.y * 32, b = blockIdx.z;
    const int tx = threadIdx.x & 31, ty = threadIdx.x >> 5;
#pragma unroll
    for (int i = 0; i < 4; i++)
        tl[ty + i * 8][tx] = Vp[((size_t)(b * LK + k0 + ty + i * 8)) * DM + d0 + tx];
    __syncthreads();
#pragma unroll
    for (int i = 0; i < 4; i++)
        Vt[((size_t)(b * DM + d0 + ty + i * 8)) * LK + k0 + tx] = tl[tx][ty + i * 8];
}

// ============================================================================
// Fused flash attention (tf32 MMA, online softmax, fused bias/mask).
// CTA: 128 queries x (head,batch). 8 warps, warp = 16 query rows.
// Loop over 32 key tiles of 64. Q resident; K/V double-buffered cp.async.
// Smem bytes: Q[0,32768) K0[32768) V0[49152) K1[65536) V1[81920)
//             P[98304,131072) btm[131072,+3600)
// ============================================================================
__global__ __launch_bounds__(256, 1) void flash_attn_tf32(
    const float* __restrict__ Qp, const float* __restrict__ Kp,
    const float* __restrict__ Vt, const int* __restrict__ b_idx,
    const int* __restrict__ mask, const float* __restrict__ b_table,
    float* __restrict__ Ao)
{
    extern __shared__ float smem[];
    const uint32_t sb = s_u32(smem);
    const uint32_t sQ = sb;
    const uint32_t sKb[2] = { sb + 32768, sb + 65536 };
    const uint32_t sVb[2] = { sb + 49152, sb + 81920 };
    const uint32_t sP = sb + 98304;
    float* btm = smem + 131072 / 4;

    const int tid = threadIdx.x;
    const int h = blockIdx.x, b = blockIdx.z;
    const int m0 = blockIdx.y * 128;
    const int l = tid & 31, w = tid >> 5;
    const int mw = w * 16;
    const int lx = l & 7;

    for (int i = tid; i < VOCAB_B; i += 256) btm[i] = b_table[i * NH + h];

    const float* Qg = Qp + ((size_t)(b * LQ + m0)) * DM + h * DK;
    const float* Kg = Kp + ((size_t)(b * LK)) * DM + h * DK;
    const float* Vg = Vt + ((size_t)(b * DM + h * DK)) * LK;

    // stage Q (128 rows x 64 floats, swizzled)
#pragma unroll
    for (int i = 0; i < 8; i++) {
        int gi = tid + i * 256;
        int r = gi >> 4, g = gi & 15;
        CP16(sQ + r * 256 + (((g ^ (r & 7)) << 4)), Qg + (size_t)r * DM + g * 4);
    }

#define STAGE_KV(IT, BUF) do {                                                 \
    const float* Ksrc_ = Kg + (size_t)((IT) * 64) * DM;                        \
    const float* Vsrc_ = Vg + (IT) * 64;                                       \
    _Pragma("unroll")                                                          \
    for (int i_ = 0; i_ < 4; i_++) {                                           \
        int gi_ = tid + i_ * 256;                                              \
        int r_ = gi_ >> 4, g_ = gi_ & 15;                                      \
        CP16(sKb[BUF] + r_ * 256 + (((g_ ^ (r_ & 7)) << 4)),                   \
             Ksrc_ + (size_t)r_ * DM + g_ * 4);                                \
    }                                                                          \
    _Pragma("unroll")                                                          \
    for (int i_ = 0; i_ < 4; i_++) {                                           \
        int gi_ = tid + i_ * 256;                                              \
        int r_ = gi_ >> 4, g_ = gi_ & 15;                                      \
        CP16(sVb[BUF] + r_ * 256 + (((g_ ^ (r_ & 7)) << 4)),                   \
             Vsrc_ + (size_t)r_ * LK + g_ * 4);                                \
    }                                                                          \
} while (0)

    STAGE_KV(0, 0);
    CPCOMMIT;

    uint32_t aq[8][4];       // Q fragments (loaded once)
    float oacc[8][4];
#pragma unroll
    for (int nf = 0; nf < 8; nf++)
#pragma unroll
        for (int r = 0; r < 4; r++) oacc[nf][r] = 0.f;
    float mr0 = -CUDART_INF_F, mr1 = -CUDART_INF_F;
    float sr0 = 0.f, sr1 = 0.f;

    int buf = 0;
    for (int it = 0; it < LK / 64; ++it) {
        if (it + 1 < LK / 64) { STAGE_KV(it + 1, buf ^ 1); CPCOMMIT; CPWAIT1; }
        else                  { CPWAIT0; }
        __syncthreads();

        if (it == 0) {
#pragma unroll
            for (int kg = 0; kg < 8; kg++) {
                uint32_t ad = sQ + (mw + (l & 15)) * 256 +
                              (((2 * kg + (l >> 4)) ^ lx) << 4);
                LDSM4(aq[kg][0], aq[kg][1], aq[kg][2], aq[kg][3], ad);
                CVT_TF32(aq[kg][0]); CVT_TF32(aq[kg][1]);
                CVT_TF32(aq[kg][2]); CVT_TF32(aq[kg][3]);
            }
        }

        // ---- S = Q K^T ----
        float sval[8][4];
#pragma unroll
        for (int nf = 0; nf < 8; nf++)
#pragma unroll
            for (int r = 0; r < 4; r++) sval[nf][r] = 0.f;

#pragma unroll
        for (int s = 0; s < 8; s += 2) {
#pragma unroll
            for (int nf = 0; nf < 8; nf++) {
                uint32_t kb[4];
                uint32_t ad = sKb[buf] + (nf * 8 + lx) * 256 +
                              (((2 * s + ((l >> 3) & 3)) ^ lx) << 4);
                LDSM4(kb[0], kb[1], kb[2], kb[3], ad);
                CVT_TF32(kb[0]); CVT_TF32(kb[1]); CVT_TF32(kb[2]); CVT_TF32(kb[3]);
                MMA_TF32(sval[nf], aq[s],     kb[0], kb[1]);
                MMA_TF32(sval[nf], aq[s + 1], kb[2], kb[3]);
            }
        }

        // ---- epilogue: scale + bias gather + mask ----
        {
            const int r0 = m0 + mw + (l >> 2);
            const int cb = it * 64 + (l & 3) * 2;
#pragma unroll
            for (int nf = 0; nf < 8; nf++) {
                size_t g0 = ((size_t)(b * LQ + r0)) * LK + cb + nf * 8;
                size_t g1 = g0 + (size_t)8 * LK;
                int2 ix0 = *(const int2*)&b_idx[g0];
                int2 mk0 = *(const int2*)&mask[g0];
                int2 ix1 = *(const int2*)&b_idx[g1];
                int2 mk1 = *(const int2*)&mask[g1];
                sval[nf][0] = mk0.x ? sval[nf][0] * 0.125f + btm[ix0.x] : -1e9f;
                sval[nf][1] = mk0.y ? sval[nf][1] * 0.125f + btm[ix0.y] : -1e9f;
                sval[nf][2] = mk1.x ? sval[nf][2] * 0.125f + btm[ix1.x] : -1e9f;
                sval[nf][3] = mk1.y ? sval[nf][3] * 0.125f + btm[ix1.y] : -1e9f;
            }
        }

        // ---- online softmax ----
        float tm0 = -CUDART_INF_F, tm1 = -CUDART_INF_F;
#pragma unroll
        for (int nf = 0; nf < 8; nf++) {
            tm0 = fmaxf(tm0, fmaxf(sval[nf][0], sval[nf][1]));
            tm1 = fmaxf(tm1, fmaxf(sval[nf][2], sval[nf][3]));
        }
#pragma unroll
        for (int o = 1; o < 4; o <<= 1) {
            tm0 = fmaxf(tm0, __shfl_xor_sync(0xffffffffu, tm0, o));
            tm1 = fmaxf(tm1, __shfl_xor_sync(0xffffffffu, tm1, o));
        }
        float mn0 = fmaxf(mr0, tm0), mn1 = fmaxf(mr1, tm1);
        float al0 = __expf(mr0 - mn0), al1 = __expf(mr1 - mn1);
        mr0 = mn0; mr1 = mn1;

        float ts0 = 0.f, ts1 = 0.f;
#pragma unroll
        for (int nf = 0; nf < 8; nf++) {
            sval[nf][0] = __expf(sval[nf][0] - mn0);
            sval[nf][1] = __expf(sval[nf][1] - mn0);
            sval[nf][2] = __expf(sval[nf][2] - mn1);
            sval[nf][3] = __expf(sval[nf][3] - mn1);
            ts0 += sval[nf][0] + sval[nf][1];
            ts1 += sval[nf][2] + sval[nf][3];
        }
#pragma unroll
        for (int o = 1; o < 4; o <<= 1) {
            ts0 += __shfl_xor_sync(0xffffffffu, ts0, o);
            ts1 += __shfl_xor_sync(0xffffffffu, ts1, o);
        }
        sr0 = sr0 * al0 + ts0;
        sr1 = sr1 * al1 + ts1;
#pragma unroll
        for (int nf = 0; nf < 8; nf++) {
            oacc[nf][0] *= al0; oacc[nf][1] *= al0;
            oacc[nf][2] *= al1; oacc[nf][3] *= al1;
        }

        // ---- P -> smem (per-warp patch), then A-frags for PV ----
        {
            const uint32_t pb = sP + w * 4096;
            const int rs0 = l >> 2;
            const uint32_t boff = ((l & 1) << 3);
            __syncwarp();
#pragma unroll
            for (int nf = 0; nf < 8; nf++) {
                int g = nf * 2 + ((l & 3) >> 1);
                uint32_t a0 = pb + rs0 * 256 + (((g ^ rs0) << 4)) + boff;
                uint32_t a1 = pb + (rs0 + 8) * 256 + (((g ^ rs0) << 4)) + boff;
                float2 p0 = { sval[nf][0], sval[nf][1] };
                float2 p1 = { sval[nf][2], sval[nf][3] };
                *(float2*)(smem + ((a0 - sb) >> 2)) = p0;
                *(float2*)(smem + ((a1 - sb) >> 2)) = p1;
            }
            __syncwarp();
        }

        uint32_t pa[8][4];
#pragma unroll
        for (int kg = 0; kg < 8; kg++) {
            uint32_t ad = sP + w * 4096 + (l & 15) * 256 +
                          (((2 * kg + (l >> 4)) ^ lx) << 4);
            LDSM4(pa[kg][0], pa[kg][1], pa[kg][2], pa[kg][3], ad);
            CVT_TF32(pa[kg][0]); CVT_TF32(pa[kg][1]);
            CVT_TF32(pa[kg][2]); CVT_TF32(pa[kg][3]);
        }

        // ---- O += P V ----
#pragma unroll
        for (int s = 0; s < 8; s += 2) {
#pragma unroll
            for (int nf = 0; nf < 8; nf++) {
                uint32_t bv[4];
                uint32_t ad = sVb[buf] + (nf * 8 + lx) * 256 +
                              (((2 * s + ((l >> 3) & 3)) ^ lx) << 4);
                LDSM4(bv[0], bv[1], bv[2], bv[3], ad);
                CVT_TF32(bv[0]); CVT_TF32(bv[1]); CVT_TF32(bv[2]); CVT_TF32(bv[3]);
                MMA_TF32(oacc[nf], pa[s],     bv[0], bv[1]);
                MMA_TF32(oacc[nf], pa[s + 1], bv[2], bv[3]);
            }
        }

        __syncthreads();
        buf ^= 1;
    }
#undef STAGE_KV

    // ---- write O / sum ----
    {
        const float i0 = 1.f / sr0, i1 = 1.f / sr1;
        const int r0 = m0 + mw + (l >> 2);
#pragma unroll
        for (int nf = 0; nf < 8; nf++) {
            int col = h * DK + nf * 8 + (l & 3) * 2;
            float2 o0 = { oacc[nf][0] * i0, oacc[nf][1] * i0 };
            float2 o1 = { oacc[nf][2] * i1, oacc[nf][3] * i1 };
            *(float2*)&Ao[((size_t)(b * LQ + r0)) * DM + col]     = o0;
            *(float2*)&Ao[((size_t)(b * LQ + r0 + 8)) * DM + col] = o1;
        }
    }
}

// ---------------------------------------------------------------------------
extern "C" void kernel_launch(void* const* d_in, const int* in_sizes, int n_in,
                              void* d_out, int out_size)
{
    const float* q       = (const float*)d_in[0];
    const float* k       = (const float*)d_in[1];
    const float* v       = (const float*)d_in[2];
    const int*   b_idx   = (const int*)  d_in[3];
    const int*   mask    = (const int*)  d_in[4];
    const float* Wq      = (const float*)d_in[5];
    const float* bq      = (const float*)d_in[6];
    const float* Wk      = (const float*)d_in[7];
    const float* bk      = (const float*)d_in[8];
    const float* Wv      = (const float*)d_in[9];
    const float* bv      = (const float*)d_in[10];
    const float* Wo      = (const float*)d_in[11];
    const float* bo      = (const float*)d_in[12];
    const float* b_table = (const float*)d_in[13];
    float* out = (float*)d_out;

    void *Qp_, *Kp_, *Vp_, *Vt_, *Ao_;
    cudaGetSymbolAddress(&Qp_, g_Qp);
    cudaGetSymbolAddress(&Kp_, g_Kp);
    cudaGetSymbolAddress(&Vp_, g_Vp);
    cudaGetSymbolAddress(&Vt_, g_Vt);
    cudaGetSymbolAddress(&Ao_, g_Ao);
    float* Qp = (float*)Qp_;
    float* Kp = (float*)Kp_;
    float* Vp = (float*)Vp_;
    float* Vt = (float*)Vt_;
    float* Ao = (float*)Ao_;

    static int attr_set = 0;
    if (!attr_set) {
        cudaFuncSetAttribute(gemm_bt_tf32,    cudaFuncAttributeMaxDynamicSharedMemorySize, 65536);
        cudaFuncSetAttribute(flash_attn_tf32, cudaFuncAttributeMaxDynamicSharedMemorySize, 135168);
        attr_set = 1;
    }

    // projections
    gemm_bt_tf32<<<dim3(DM / 128, (BSZ * LQ) / 128), 256, 65536>>>(q, Wq, bq, Qp, BSZ * LQ, DM, DM);
    gemm_bt_tf32<<<dim3(DM / 128, (BSZ * LK) / 128), 256, 65536>>>(k, Wk, bk, Kp, BSZ * LK, DM, DM);
    gemm_bt_tf32<<<dim3(DM / 128, (BSZ * LK) / 128), 256, 65536>>>(v, Wv, bv, Vp, BSZ * LK, DM, DM);
    vtrans_kernel<<<dim3(LK / 32, DM / 32, BSZ), 256>>>(Vp, Vt);

    // fused attention (h fastest for b_idx/mask L2 reuse)
    flash_attn_tf32<<<dim3(NH, LQ / 128, BSZ), 256, 135168>>>(
        Qp, Kp, Vt, b_idx, mask, b_table, Ao);

    // output projection
    gemm_bt_tf32<<<dim3(DM / 128, (BSZ * LQ) / 128), 256, 65536>>>(Ao, Wo, bo, out, BSZ * LQ, DM, DM);
}

// round 5
// speedup vs baseline: 6.8980x; 1.0172x over previous
#include <cuda_runtime.h>
#include <cstdint>
#include <math_constants.h>

#define BSZ 4
#define LQ  512
#define LK  2048
#define DM  1024
#define NH  16
#define DK  64
#define VOCAB_B 900

// ---------------- scratch (static device memory; no runtime alloc) ----------
__device__ float g_Qp[BSZ * LQ * DM];
__device__ float g_Kp[BSZ * LK * DM];
__device__ float g_Vp[BSZ * LK * DM];
__device__ float g_Vt[BSZ * DM * LK];            // V transposed: [b][dm][k]
__device__ float g_Ao[BSZ * LQ * DM];
__device__ float g_qr[BSZ * LQ * DM];            // tf32-rounded inputs
__device__ float g_kr[BSZ * LK * DM];
__device__ float g_vr[BSZ * LK * DM];
__device__ float g_Wr[4 * DM * DM];              // rounded Wq,Wk,Wv,Wo

// ---------------- PTX helpers ----------------------------------------------
__device__ __forceinline__ uint32_t s_u32(const void* p) {
    uint32_t a;
    asm("{.reg .u64 t; cvta.to.shared.u64 t, %1; cvt.u32.u64 %0, t;}"
        : "=r"(a) : "l"(p));
    return a;
}

__device__ __forceinline__ float rtf32(float x) {
    uint32_t u = __float_as_uint(x);
    asm("cvt.rna.tf32.f32 %0,%0;" : "+r"(u));
    return __uint_as_float(u);
}

#define LDSM4(R0,R1,R2,R3,ADDR) \
    asm volatile("ldmatrix.sync.aligned.m8n8.x4.shared.b16 {%0,%1,%2,%3},[%4];" \
        : "=r"(R0),"=r"(R1),"=r"(R2),"=r"(R3) : "r"(ADDR))

#define CVT_TF32(T) asm volatile("cvt.rna.tf32.f32 %0,%0;" : "+r"(T))

#define MMA_TF32(D,A,B0,B1) \
    asm volatile("mma.sync.aligned.m16n8k8.row.col.f32.tf32.tf32.f32 " \
        "{%0,%1,%2,%3},{%4,%5,%6,%7},{%8,%9},{%0,%1,%2,%3};" \
        : "+f"(D[0]),"+f"(D[1]),"+f"(D[2]),"+f"(D[3]) \
        : "r"(A[0]),"r"(A[1]),"r"(A[2]),"r"(A[3]),"r"(B0),"r"(B1))

#define CP16(DST,SRC) \
    asm volatile("cp.async.cg.shared.global [%0],[%1],16;" :: "r"(DST),"l"(SRC))
#define CPCOMMIT  asm volatile("cp.async.commit_group;")
#define CPWAIT0   asm volatile("cp.async.wait_group 0;")
#define CPWAIT1   asm volatile("cp.async.wait_group 1;")

// ============================================================================
// tf32 rounding pass (vectorized): out[i] = round_tf32(in[i])
// ============================================================================
__global__ __launch_bounds__(256) void round_tf32_kernel(
    const float4* __restrict__ in, float4* __restrict__ out, int n4)
{
    int i = blockIdx.x * 256 + threadIdx.x;
    if (i < n4) {
        float4 v = in[i];
        v.x = rtf32(v.x); v.y = rtf32(v.y);
        v.z = rtf32(v.z); v.w = rtf32(v.w);
        out[i] = v;
    }
}

// ============================================================================
// tf32 GEMM: C = A @ B^T + bias. Inputs PRE-ROUNDED to tf32 (no CVT inside).
// rnd != 0: round outputs to tf32 (for tensors consumed by later tf32 MMAs).
// ============================================================================
__global__ __launch_bounds__(256, 2) void gemm_bt_tf32(
    const float* __restrict__ A, const float* __restrict__ B,
    const float* __restrict__ bias, float* __restrict__ C,
    int M, int N, int K, int rnd)
{
    extern __shared__ float smem[];
    const uint32_t sbase = s_u32(smem);
    const int tid = threadIdx.x;
    const int m0 = blockIdx.y * 128, n0 = blockIdx.x * 128;
    const int l  = tid & 31, w = tid >> 5;
    const int mw = (w >> 2) * 64, nw = (w & 3) * 32;
    const int lrow = l & 15, lq = l >> 4, lx = l & 7;
    const int sm = tid >> 3, sg = tid & 7;

    float acc[4][4][4];
#pragma unroll
    for (int i = 0; i < 4; i++)
#pragma unroll
        for (int j = 0; j < 4; j++)
#pragma unroll
            for (int r = 0; r < 4; r++) acc[i][j][r] = 0.f;

    const int NIT = K >> 5;

#define STAGE_G(IT, BUF) do {                                                  \
    uint32_t sA_ = sbase + (BUF) * 32768;                                      \
    uint32_t sB_ = sA_ + 16384;                                                \
    const float* Ag_ = A + (size_t)(m0) * K + (IT) * 32;                       \
    const float* Bg_ = B + (size_t)(n0) * K + (IT) * 32;                       \
    _Pragma("unroll")                                                          \
    for (int i_ = 0; i_ < 4; i_++) {                                           \
        int r_ = sm + i_ * 32;                                                 \
        CP16(sA_ + r_ * 128 + (((sg ^ (r_ & 7)) << 4)),                        \
             Ag_ + (size_t)r_ * K + sg * 4);                                   \
    }                                                                          \
    _Pragma("unroll")                                                          \
    for (int i_ = 0; i_ < 4; i_++) {                                           \
        int r_ = sm + i_ * 32;                                                 \
        CP16(sB_ + r_ * 128 + (((sg ^ (r_ & 7)) << 4)),                        \
             Bg_ + (size_t)r_ * K + sg * 4);                                   \
    }                                                                          \
} while (0)

    STAGE_G(0, 0);
    CPCOMMIT;

    int buf = 0;
    for (int it = 0; it < NIT; ++it) {
        if (it + 1 < NIT) { STAGE_G(it + 1, buf ^ 1); CPCOMMIT; CPWAIT1; }
        else              { CPWAIT0; }
        __syncthreads();

        const uint32_t sA = sbase + buf * 32768;
        const uint32_t sB = sA + 16384;
        const uint32_t aAdr0 = sA + (mw + lrow) * 128;
        const uint32_t bAdr0 = sB + (nw + (l & 7)) * 128;

#pragma unroll
        for (int s = 0; s < 4; s += 2) {
            uint32_t b[4][4];
#pragma unroll
            for (int nf = 0; nf < 4; nf++) {
                uint32_t ad = bAdr0 + nf * 1024 +
                              (((2 * s + ((l >> 3) & 3)) ^ lx) << 4);
                LDSM4(b[nf][0], b[nf][1], b[nf][2], b[nf][3], ad);
            }
#pragma unroll
            for (int ss = 0; ss < 2; ss++) {
                uint32_t a[4][4];
#pragma unroll
                for (int mf = 0; mf < 4; mf++) {
                    uint32_t ad = aAdr0 + mf * 2048 +
                                  (((2 * (s + ss) + lq) ^ lx) << 4);
                    LDSM4(a[mf][0], a[mf][1], a[mf][2], a[mf][3], ad);
                }
#pragma unroll
                for (int mf = 0; mf < 4; mf++)
#pragma unroll
                    for (int nf = 0; nf < 4; nf++)
                        MMA_TF32(acc[mf][nf], a[mf], b[nf][2 * ss], b[nf][2 * ss + 1]);
            }
        }
        __syncthreads();
        buf ^= 1;
    }
#undef STAGE_G

#pragma unroll
    for (int mf = 0; mf < 4; mf++) {
        int row = m0 + mw + mf * 16 + (l >> 2);
#pragma unroll
        for (int nf = 0; nf < 4; nf++) {
            int col = n0 + nw + nf * 8 + (l & 3) * 2;
            float2 bb = *(const float2*)&bias[col];
            float2 o0, o1;
            o0.x = acc[mf][nf][0] + bb.x; o0.y = acc[mf][nf][1] + bb.y;
            o1.x = acc[mf][nf][2] + bb.x; o1.y = acc[mf][nf][3] + bb.y;
            if (rnd) {
                o0.x = rtf32(o0.x); o0.y = rtf32(o0.y);
                o1.x = rtf32(o1.x); o1.y = rtf32(o1.y);
            }
            *(float2*)&C[(size_t)row * N + col]       = o0;
            *(float2*)&C[(size_t)(row + 8) * N + col] = o1;
        }
    }
}

// ============================================================================
// V transpose: Vt[b][d][k] = Vp[b*LK + k][d]    (Vp already tf32-rounded)
// ============================================================================
__global__ __launch_bounds__(256) void vtrans_kernel(
    const float* __restrict__ Vp, float* __restrict__ Vt)
{
    __shared__ float tl[32][33];
    const int k0 = blockIdx.x * 32, d0 = blockIdx.y * 32, b = blockIdx.z;
    const int tx = threadIdx.x & 31, ty = threadIdx.x >> 5;
#pragma unroll
    for (int i = 0; i < 4; i++)
        tl[ty + i * 8][tx] = Vp[((size_t)(b * LK + k0 + ty + i * 8)) * DM + d0 + tx];
    __syncthreads();
#pragma unroll
    for (int i = 0; i < 4; i++)
        Vt[((size_t)(b * DM + d0 + ty + i * 8)) * LK + k0 + tx] = tl[tx][ty + i * 8];
}

// ============================================================================
// Fused flash attention. CTA: 64 queries, 4 warps (128 thr), 2 CTAs/SM.
// All tensor operands pre-rounded tf32 (no CVT except P after exp).
// Smem bytes: Q/P[0,16384) K0[16384) V0[32768) K1[49152) V1[65536)
//             btm[81920,+3600)  => 85520 total
// ============================================================================
__global__ __launch_bounds__(128, 2) void flash_attn_tf32(
    const float* __restrict__ Qp, const float* __restrict__ Kp,
    const float* __restrict__ Vt, const int* __restrict__ b_idx,
    const int* __restrict__ mask, const float* __restrict__ b_table,
    float* __restrict__ Ao)
{
    extern __shared__ float smem[];
    const uint32_t sb = s_u32(smem);
    const uint32_t sQ = sb;                       // aliased by P after Q consumed
    const uint32_t sKb[2] = { sb + 16384, sb + 49152 };
    const uint32_t sVb[2] = { sb + 32768, sb + 65536 };
    float* btm = smem + 81920 / 4;

    const int tid = threadIdx.x;
    const int h = blockIdx.x, b = blockIdx.z;
    const int m0 = blockIdx.y * 64;
    const int l = tid & 31, w = tid >> 5;
    const int mw = w * 16;
    const int lx = l & 7;

    for (int i = tid; i < VOCAB_B; i += 128) btm[i] = b_table[i * NH + h];

    const float* Qg = Qp + ((size_t)(b * LQ + m0)) * DM + h * DK;
    const float* Kg = Kp + ((size_t)(b * LK)) * DM + h * DK;
    const float* Vg = Vt + ((size_t)(b * DM + h * DK)) * LK;

    // stage Q (64 rows x 64 floats, swizzled)
#pragma unroll
    for (int i = 0; i < 8; i++) {
        int gi = tid + i * 128;
        int r = gi >> 4, g = gi & 15;
        CP16(sQ + r * 256 + (((g ^ (r & 7)) << 4)), Qg + (size_t)r * DM + g * 4);
    }

#define STAGE_KV(IT, BUF) do {                                                 \
    const float* Ksrc_ = Kg + (size_t)((IT) * 64) * DM;                        \
    const float* Vsrc_ = Vg + (IT) * 64;                                       \
    _Pragma("unroll")                                                          \
    for (int i_ = 0; i_ < 8; i_++) {                                           \
        int gi_ = tid + i_ * 128;                                              \
        int r_ = gi_ >> 4, g_ = gi_ & 15;                                      \
        CP16(sKb[BUF] + r_ * 256 + (((g_ ^ (r_ & 7)) << 4)),                   \
             Ksrc_ + (size_t)r_ * DM + g_ * 4);                                \
    }                                                                          \
    _Pragma("unroll")                                                          \
    for (int i_ = 0; i_ < 8; i_++) {                                           \
        int gi_ = tid + i_ * 128;                                              \
        int r_ = gi_ >> 4, g_ = gi_ & 15;                                      \
        CP16(sVb[BUF] + r_ * 256 + (((g_ ^ (r_ & 7)) << 4)),                   \
             Vsrc_ + (size_t)r_ * LK + g_ * 4);                                \
    }                                                                          \
} while (0)

    STAGE_KV(0, 0);
    CPCOMMIT;

    uint32_t aq[8][4];
    float oacc[8][4];
#pragma unroll
    for (int nf = 0; nf < 8; nf++)
#pragma unroll
        for (int r = 0; r < 4; r++) oacc[nf][r] = 0.f;
    float mr0 = -CUDART_INF_F, mr1 = -CUDART_INF_F;
    float sr0 = 0.f, sr1 = 0.f;

    int buf = 0;
    for (int it = 0; it < LK / 64; ++it) {
        if (it + 1 < LK / 64) { STAGE_KV(it + 1, buf ^ 1); CPCOMMIT; CPWAIT1; }
        else                  { CPWAIT0; }
        __syncthreads();

        if (it == 0) {
            // consume Q into registers; region becomes the P patch afterwards
#pragma unroll
            for (int kg = 0; kg < 8; kg++) {
                uint32_t ad = sQ + (mw + (l & 15)) * 256 +
                              (((2 * kg + (l >> 4)) ^ lx) << 4);
                LDSM4(aq[kg][0], aq[kg][1], aq[kg][2], aq[kg][3], ad);
            }
        }

        // ---- S = Q K^T ----
        float sval[8][4];
#pragma unroll
        for (int nf = 0; nf < 8; nf++)
#pragma unroll
            for (int r = 0; r < 4; r++) sval[nf][r] = 0.f;

#pragma unroll
        for (int s = 0; s < 8; s += 2) {
#pragma unroll
            for (int nf = 0; nf < 8; nf++) {
                uint32_t kb[4];
                uint32_t ad = sKb[buf] + (nf * 8 + lx) * 256 +
                              (((2 * s + ((l >> 3) & 3)) ^ lx) << 4);
                LDSM4(kb[0], kb[1], kb[2], kb[3], ad);
                MMA_TF32(sval[nf], aq[s],     kb[0], kb[1]);
                MMA_TF32(sval[nf], aq[s + 1], kb[2], kb[3]);
            }
        }

        // ---- scale + bias gather + mask ----
        {
            const int r0 = m0 + mw + (l >> 2);
            const int cb = it * 64 + (l & 3) * 2;
#pragma unroll
            for (int nf = 0; nf < 8; nf++) {
                size_t g0 = ((size_t)(b * LQ + r0)) * LK + cb + nf * 8;
                size_t g1 = g0 + (size_t)8 * LK;
                int2 ix0 = *(const int2*)&b_idx[g0];
                int2 mk0 = *(const int2*)&mask[g0];
                int2 ix1 = *(const int2*)&b_idx[g1];
                int2 mk1 = *(const int2*)&mask[g1];
                sval[nf][0] = mk0.x ? sval[nf][0] * 0.125f + btm[ix0.x] : -1e9f;
                sval[nf][1] = mk0.y ? sval[nf][1] * 0.125f + btm[ix0.y] : -1e9f;
                sval[nf][2] = mk1.x ? sval[nf][2] * 0.125f + btm[ix1.x] : -1e9f;
                sval[nf][3] = mk1.y ? sval[nf][3] * 0.125f + btm[ix1.y] : -1e9f;
            }
        }

        // ---- online softmax ----
        float tm0 = -CUDART_INF_F, tm1 = -CUDART_INF_F;
#pragma unroll
        for (int nf = 0; nf < 8; nf++) {
            tm0 = fmaxf(tm0, fmaxf(sval[nf][0], sval[nf][1]));
            tm1 = fmaxf(tm1, fmaxf(sval[nf][2], sval[nf][3]));
        }
#pragma unroll
        for (int o = 1; o < 4; o <<= 1) {
            tm0 = fmaxf(tm0, __shfl_xor_sync(0xffffffffu, tm0, o));
            tm1 = fmaxf(tm1, __shfl_xor_sync(0xffffffffu, tm1, o));
        }
        float mn0 = fmaxf(mr0, tm0), mn1 = fmaxf(mr1, tm1);
        float al0 = __expf(mr0 - mn0), al1 = __expf(mr1 - mn1);
        mr0 = mn0; mr1 = mn1;

        float ts0 = 0.f, ts1 = 0.f;
#pragma unroll
        for (int nf = 0; nf < 8; nf++) {
            sval[nf][0] = __expf(sval[nf][0] - mn0);
            sval[nf][1] = __expf(sval[nf][1] - mn0);
            sval[nf][2] = __expf(sval[nf][2] - mn1);
            sval[nf][3] = __expf(sval[nf][3] - mn1);
            ts0 += sval[nf][0] + sval[nf][1];
            ts1 += sval[nf][2] + sval[nf][3];
        }
#pragma unroll
        for (int o = 1; o < 4; o <<= 1) {
            ts0 += __shfl_xor_sync(0xffffffffu, ts0, o);
            ts1 += __shfl_xor_sync(0xffffffffu, ts1, o);
        }
        sr0 = sr0 * al0 + ts0;
        sr1 = sr1 * al1 + ts1;
#pragma unroll
        for (int nf = 0; nf < 8; nf++) {
            oacc[nf][0] *= al0; oacc[nf][1] *= al0;
            oacc[nf][2] *= al1; oacc[nf][3] *= al1;
        }

        // ---- P -> per-warp patch (aliases this warp's Q rows) ----
        {
            const uint32_t pb = sQ + w * 4096;
            const int rs0 = l >> 2;
            const uint32_t boff = ((l & 1) << 3);
            __syncwarp();
#pragma unroll
            for (int nf = 0; nf < 8; nf++) {
                int g = nf * 2 + ((l & 3) >> 1);
                uint32_t a0 = pb + rs0 * 256 + (((g ^ rs0) << 4)) + boff;
                uint32_t a1 = pb + (rs0 + 8) * 256 + (((g ^ rs0) << 4)) + boff;
                float2 p0 = { sval[nf][0], sval[nf][1] };
                float2 p1 = { sval[nf][2], sval[nf][3] };
                *(float2*)(smem + ((a0 - sb) >> 2)) = p0;
                *(float2*)(smem + ((a1 - sb) >> 2)) = p1;
            }
            __syncwarp();
        }

        uint32_t pa[8][4];
#pragma unroll
        for (int kg = 0; kg < 8; kg++) {
            uint32_t ad = sQ + w * 4096 + (l & 15) * 256 +
                          (((2 * kg + (l >> 4)) ^ lx) << 4);
            LDSM4(pa[kg][0], pa[kg][1], pa[kg][2], pa[kg][3], ad);
            CVT_TF32(pa[kg][0]); CVT_TF32(pa[kg][1]);
            CVT_TF32(pa[kg][2]); CVT_TF32(pa[kg][3]);
        }

        // ---- O += P V ----
#pragma unroll
        for (int s = 0; s < 8; s += 2) {
#pragma unroll
            for (int nf = 0; nf < 8; nf++) {
                uint32_t bv[4];
                uint32_t ad = sVb[buf] + (nf * 8 + lx) * 256 +
                              (((2 * s + ((l >> 3) & 3)) ^ lx) << 4);
                LDSM4(bv[0], bv[1], bv[2], bv[3], ad);
                MMA_TF32(oacc[nf], pa[s],     bv[0], bv[1]);
                MMA_TF32(oacc[nf], pa[s + 1], bv[2], bv[3]);
            }
        }

        __syncthreads();
        buf ^= 1;
    }
#undef STAGE_KV

    // ---- write O (rounded to tf32 for the output projection) ----
    {
        const float i0 = 1.f / sr0, i1 = 1.f / sr1;
        const int r0 = m0 + mw + (l >> 2);
#pragma unroll
        for (int nf = 0; nf < 8; nf++) {
            int col = h * DK + nf * 8 + (l & 3) * 2;
            float2 o0 = { rtf32(oacc[nf][0] * i0), rtf32(oacc[nf][1] * i0) };
            float2 o1 = { rtf32(oacc[nf][2] * i1), rtf32(oacc[nf][3] * i1) };
            *(float2*)&Ao[((size_t)(b * LQ + r0)) * DM + col]     = o0;
            *(float2*)&Ao[((size_t)(b * LQ + r0 + 8)) * DM + col] = o1;
        }
    }
}

// ---------------------------------------------------------------------------
extern "C" void kernel_launch(void* const* d_in, const int* in_sizes, int n_in,
                              void* d_out, int out_size)
{
    const float* q       = (const float*)d_in[0];
    const float* k       = (const float*)d_in[1];
    const float* v       = (const float*)d_in[2];
    const int*   b_idx   = (const int*)  d_in[3];
    const int*   mask    = (const int*)  d_in[4];
    const float* Wq      = (const float*)d_in[5];
    const float* bq      = (const float*)d_in[6];
    const float* Wk      = (const float*)d_in[7];
    const float* bk      = (const float*)d_in[8];
    const float* Wv      = (const float*)d_in[9];
    const float* bv      = (const float*)d_in[10];
    const float* Wo      = (const float*)d_in[11];
    const float* bo      = (const float*)d_in[12];
    const float* b_table = (const float*)d_in[13];
    float* out = (float*)d_out;

    void *Qp_, *Kp_, *Vp_, *Vt_, *Ao_, *qr_, *kr_, *vr_, *Wr_;
    cudaGetSymbolAddress(&Qp_, g_Qp);
    cudaGetSymbolAddress(&Kp_, g_Kp);
    cudaGetSymbolAddress(&Vp_, g_Vp);
    cudaGetSymbolAddress(&Vt_, g_Vt);
    cudaGetSymbolAddress(&Ao_, g_Ao);
    cudaGetSymbolAddress(&qr_, g_qr);
    cudaGetSymbolAddress(&kr_, g_kr);
    cudaGetSymbolAddress(&vr_, g_vr);
    cudaGetSymbolAddress(&Wr_, g_Wr);
    float* Qp = (float*)Qp_;
    float* Kp = (float*)Kp_;
    float* Vp = (float*)Vp_;
    float* Vt = (float*)Vt_;
    float* Ao = (float*)Ao_;
    float* qr = (float*)qr_;
    float* kr = (float*)kr_;
    float* vr = (float*)vr_;
    float* Wr = (float*)Wr_;

    static int attr_set = 0;
    if (!attr_set) {
        cudaFuncSetAttribute(gemm_bt_tf32,    cudaFuncAttributeMaxDynamicSharedMemorySize, 65536);
        cudaFuncSetAttribute(flash_attn_tf32, cudaFuncAttributeMaxDynamicSharedMemorySize, 85520);
        attr_set = 1;
    }

    // pre-round all tf32 MMA operands (bit-identical to in-loop cvt.rna)
    const int NQ4 = BSZ * LQ * DM / 4, NK4 = BSZ * LK * DM / 4, NW4 = DM * DM / 4;
    round_tf32_kernel<<<(NQ4 + 255) / 256, 256>>>((const float4*)q, (float4*)qr, NQ4);
    round_tf32_kernel<<<(NK4 + 255) / 256, 256>>>((const float4*)k, (float4*)kr, NK4);
    round_tf32_kernel<<<(NK4 + 255) / 256, 256>>>((const float4*)v, (float4*)vr, NK4);
    round_tf32_kernel<<<(NW4 + 255) / 256, 256>>>((const float4*)Wq, (float4*)(Wr + 0 * DM * DM), NW4);
    round_tf32_kernel<<<(NW4 + 255) / 256, 256>>>((const float4*)Wk, (float4*)(Wr + 1 * DM * DM), NW4);
    round_tf32_kernel<<<(NW4 + 255) / 256, 256>>>((const float4*)Wv, (float4*)(Wr + 2 * DM * DM), NW4);
    round_tf32_kernel<<<(NW4 + 255) / 256, 256>>>((const float4*)Wo, (float4*)(Wr + 3 * DM * DM), NW4);

    // projections (outputs rounded for the downstream tf32 MMAs)
    gemm_bt_tf32<<<dim3(DM / 128, (BSZ * LQ) / 128), 256, 65536>>>(qr, Wr + 0 * DM * DM, bq, Qp, BSZ * LQ, DM, DM, 1);
    gemm_bt_tf32<<<dim3(DM / 128, (BSZ * LK) / 128), 256, 65536>>>(kr, Wr + 1 * DM * DM, bk, Kp, BSZ * LK, DM, DM, 1);
    gemm_bt_tf32<<<dim3(DM / 128, (BSZ * LK) / 128), 256, 65536>>>(vr, Wr + 2 * DM * DM, bv, Vp, BSZ * LK, DM, DM, 1);
    vtrans_kernel<<<dim3(LK / 32, DM / 32, BSZ), 256>>>(Vp, Vt);

    // fused attention (h fastest for b_idx/mask L2 reuse)
    flash_attn_tf32<<<dim3(NH, LQ / 64, BSZ), 128, 85520>>>(
        Qp, Kp, Vt, b_idx, mask, b_table, Ao);

    // output projection (final output: NOT rounded)
    gemm_bt_tf32<<<dim3(DM / 128, (BSZ * LQ) / 128), 256, 65536>>>(Ao, Wr + 3 * DM * DM, bo, out, BSZ * LQ, DM, DM, 0);
}

// round 6
// speedup vs baseline: 8.4252x; 1.2214x over previous
#include <cuda_runtime.h>
#include <cstdint>
#include <math_constants.h>

#define BSZ 4
#define LQ  512
#define LK  2048
#define DM  1024
#define NH  16
#define DK  64
#define VOCAB_B 900

// ---------------- scratch (static device memory; no runtime alloc) ----------
__device__ float g_Qp[BSZ * LQ * DM];
__device__ float g_Kp[BSZ * LK * DM];
__device__ float g_Vp[BSZ * LK * DM];
__device__ float g_Vt[BSZ * DM * LK];
__device__ float g_Ao[BSZ * LQ * DM];
__device__ float g_Wr[4 * DM * DM];                    // rounded Wq,Wk,Wv,Wo
__device__ unsigned short g_bm[BSZ * LQ * LK];         // packed b_idx|mask<<15

// ---------------- PTX helpers ----------------------------------------------
__device__ __forceinline__ uint32_t s_u32(const void* p) {
    uint32_t a;
    asm("{.reg .u64 t; cvta.to.shared.u64 t, %1; cvt.u32.u64 %0, t;}"
        : "=r"(a) : "l"(p));
    return a;
}

__device__ __forceinline__ float rtf32(float x) {
    uint32_t u = __float_as_uint(x);
    asm("cvt.rna.tf32.f32 %0,%0;" : "+r"(u));
    return __uint_as_float(u);
}

#define LDSM4(R0,R1,R2,R3,ADDR) \
    asm volatile("ldmatrix.sync.aligned.m8n8.x4.shared.b16 {%0,%1,%2,%3},[%4];" \
        : "=r"(R0),"=r"(R1),"=r"(R2),"=r"(R3) : "r"(ADDR))

#define CVT_TF32(T) asm volatile("cvt.rna.tf32.f32 %0,%0;" : "+r"(T))

#define MMA_TF32(D,A,B0,B1) \
    asm volatile("mma.sync.aligned.m16n8k8.row.col.f32.tf32.tf32.f32 " \
        "{%0,%1,%2,%3},{%4,%5,%6,%7},{%8,%9},{%0,%1,%2,%3};" \
        : "+f"(D[0]),"+f"(D[1]),"+f"(D[2]),"+f"(D[3]) \
        : "r"(A[0]),"r"(A[1]),"r"(A[2]),"r"(A[3]),"r"(B0),"r"(B1))

#define CP16(DST,SRC) \
    asm volatile("cp.async.cg.shared.global [%0],[%1],16;" :: "r"(DST),"l"(SRC))
#define CPCOMMIT  asm volatile("cp.async.commit_group;")
#define CPWAIT0   asm volatile("cp.async.wait_group 0;")
#define CPWAIT1   asm volatile("cp.async.wait_group 1;")

// ============================================================================
// tf32 rounding pass (weights only)
// ============================================================================
__global__ __launch_bounds__(256) void round_tf32_kernel(
    const float4* __restrict__ in, float4* __restrict__ out, int n4)
{
    int i = blockIdx.x * 256 + threadIdx.x;
    if (i < n4) {
        float4 v = in[i];
        v.x = rtf32(v.x); v.y = rtf32(v.y);
        v.z = rtf32(v.z); v.w = rtf32(v.w);
        out[i] = v;
    }
}

// ============================================================================
// pack b_idx + mask -> uint16 (idx in [0,900) | mask<<15)
// ============================================================================
__global__ __launch_bounds__(256) void pack_bm_kernel(
    const int4* __restrict__ b_idx, const int4* __restrict__ mask,
    ushort4* __restrict__ bm, int n4)
{
    int i = blockIdx.x * 256 + threadIdx.x;
    if (i < n4) {
        int4 ix = b_idx[i];
        int4 mk = mask[i];
        ushort4 o;
        o.x = (unsigned short)(ix.x | (mk.x << 15));
        o.y = (unsigned short)(ix.y | (mk.y << 15));
        o.z = (unsigned short)(ix.z | (mk.z << 15));
        o.w = (unsigned short)(ix.w | (mk.w << 15));
        bm[i] = o;
    }
}

// ============================================================================
// tf32 GEMM: C = A @ B^T + bias. B pre-rounded; CVTA: round A-frags in loop.
// RND: round outputs to tf32.
// ============================================================================
template<int CVTA, int RND>
__global__ __launch_bounds__(256, 2) void gemm_bt_tf32(
    const float* __restrict__ A, const float* __restrict__ B,
    const float* __restrict__ bias, float* __restrict__ C,
    int M, int N, int K)
{
    extern __shared__ float smem[];
    const uint32_t sbase = s_u32(smem);
    const int tid = threadIdx.x;
    const int m0 = blockIdx.y * 128, n0 = blockIdx.x * 128;
    const int l  = tid & 31, w = tid >> 5;
    const int mw = (w >> 2) * 64, nw = (w & 3) * 32;
    const int lrow = l & 15, lq = l >> 4, lx = l & 7;
    const int sm = tid >> 3, sg = tid & 7;

    float acc[4][4][4];
#pragma unroll
    for (int i = 0; i < 4; i++)
#pragma unroll
        for (int j = 0; j < 4; j++)
#pragma unroll
            for (int r = 0; r < 4; r++) acc[i][j][r] = 0.f;

    const int NIT = K >> 5;

#define STAGE_G(IT, BUF) do {                                                  \
    uint32_t sA_ = sbase + (BUF) * 32768;                                      \
    uint32_t sB_ = sA_ + 16384;                                                \
    const float* Ag_ = A + (size_t)(m0) * K + (IT) * 32;                       \
    const float* Bg_ = B + (size_t)(n0) * K + (IT) * 32;                       \
    _Pragma("unroll")                                                          \
    for (int i_ = 0; i_ < 4; i_++) {                                           \
        int r_ = sm + i_ * 32;                                                 \
        CP16(sA_ + r_ * 128 + (((sg ^ (r_ & 7)) << 4)),                        \
             Ag_ + (size_t)r_ * K + sg * 4);                                   \
    }                                                                          \
    _Pragma("unroll")                                                          \
    for (int i_ = 0; i_ < 4; i_++) {                                           \
        int r_ = sm + i_ * 32;                                                 \
        CP16(sB_ + r_ * 128 + (((sg ^ (r_ & 7)) << 4)),                        \
             Bg_ + (size_t)r_ * K + sg * 4);                                   \
    }                                                                          \
} while (0)

    STAGE_G(0, 0);
    CPCOMMIT;

    int buf = 0;
    for (int it = 0; it < NIT; ++it) {
        if (it + 1 < NIT) { STAGE_G(it + 1, buf ^ 1); CPCOMMIT; CPWAIT1; }
        else              { CPWAIT0; }
        __syncthreads();

        const uint32_t sA = sbase + buf * 32768;
        const uint32_t sB = sA + 16384;
        const uint32_t aAdr0 = sA + (mw + lrow) * 128;
        const uint32_t bAdr0 = sB + (nw + (l & 7)) * 128;

#pragma unroll
        for (int s = 0; s < 4; s += 2) {
            uint32_t b[4][4];
#pragma unroll
            for (int nf = 0; nf < 4; nf++) {
                uint32_t ad = bAdr0 + nf * 1024 +
                              (((2 * s + ((l >> 3) & 3)) ^ lx) << 4);
                LDSM4(b[nf][0], b[nf][1], b[nf][2], b[nf][3], ad);
            }
#pragma unroll
            for (int ss = 0; ss < 2; ss++) {
                uint32_t a[4][4];
#pragma unroll
                for (int mf = 0; mf < 4; mf++) {
                    uint32_t ad = aAdr0 + mf * 2048 +
                                  (((2 * (s + ss) + lq) ^ lx) << 4);
                    LDSM4(a[mf][0], a[mf][1], a[mf][2], a[mf][3], ad);
                    if (CVTA) {
                        CVT_TF32(a[mf][0]); CVT_TF32(a[mf][1]);
                        CVT_TF32(a[mf][2]); CVT_TF32(a[mf][3]);
                    }
                }
#pragma unroll
                for (int mf = 0; mf < 4; mf++)
#pragma unroll
                    for (int nf = 0; nf < 4; nf++)
                        MMA_TF32(acc[mf][nf], a[mf], b[nf][2 * ss], b[nf][2 * ss + 1]);
            }
        }
        __syncthreads();
        buf ^= 1;
    }
#undef STAGE_G

#pragma unroll
    for (int mf = 0; mf < 4; mf++) {
        int row = m0 + mw + mf * 16 + (l >> 2);
#pragma unroll
        for (int nf = 0; nf < 4; nf++) {
            int col = n0 + nw + nf * 8 + (l & 3) * 2;
            float2 bb = *(const float2*)&bias[col];
            float2 o0, o1;
            o0.x = acc[mf][nf][0] + bb.x; o0.y = acc[mf][nf][1] + bb.y;
            o1.x = acc[mf][nf][2] + bb.x; o1.y = acc[mf][nf][3] + bb.y;
            if (RND) {
                o0.x = rtf32(o0.x); o0.y = rtf32(o0.y);
                o1.x = rtf32(o1.x); o1.y = rtf32(o1.y);
            }
            *(float2*)&C[(size_t)row * N + col]       = o0;
            *(float2*)&C[(size_t)(row + 8) * N + col] = o1;
        }
    }
}

// ============================================================================
// V transpose: Vt[b][d][k] = Vp[b*LK + k][d]
// ============================================================================
__global__ __launch_bounds__(256) void vtrans_kernel(
    const float* __restrict__ Vp, float* __restrict__ Vt)
{
    __shared__ float tl[32][33];
    const int k0 = blockIdx.x * 32, d0 = blockIdx.y * 32, b = blockIdx.z;
    const int tx = threadIdx.x & 31, ty = threadIdx.x >> 5;
#pragma unroll
    for (int i = 0; i < 4; i++)
        tl[ty + i * 8][tx] = Vp[((size_t)(b * LK + k0 + ty + i * 8)) * DM + d0 + tx];
    __syncthreads();
#pragma unroll
    for (int i = 0; i < 4; i++)
        Vt[((size_t)(b * DM + d0 + ty + i * 8)) * LK + k0 + tx] = tl[tx][ty + i * 8];
}

// ============================================================================
// Fused flash attention. CTA: 64 queries, 4 warps, 2 CTAs/SM.
// bias/mask gathered from packed uint16 tile staged in smem (no LDG in loop).
// Smem bytes: Q/P[0,16384)
//   buf0: K@16384 V@32768 BM@49152(8K)   buf1: K@57344 V@73728 BM@90112(8K)
//   btm@98304 (+3600) => 101904 total
// ============================================================================
__global__ __launch_bounds__(128, 2) void flash_attn_tf32(
    const float* __restrict__ Qp, const float* __restrict__ Kp,
    const float* __restrict__ Vt, const unsigned short* __restrict__ bm,
    const float* __restrict__ b_table, float* __restrict__ Ao)
{
    extern __shared__ float smem[];
    const uint32_t sb = s_u32(smem);
    const uint32_t sQ = sb;                       // aliased by P after Q consumed
    const uint32_t sKb[2]  = { sb + 16384, sb + 57344 };
    const uint32_t sVb[2]  = { sb + 32768, sb + 73728 };
    const uint32_t sBMb[2] = { sb + 49152, sb + 90112 };
    const uint32_t bmOff[2] = { 49152, 90112 };   // byte offsets from smem base
    float* btm = smem + 98304 / 4;

    const int tid = threadIdx.x;
    const int h = blockIdx.x, b = blockIdx.z;
    const int m0 = blockIdx.y * 64;
    const int l = tid & 31, w = tid >> 5;
    const int mw = w * 16;
    const int lx = l & 7;

    for (int i = tid; i < VOCAB_B; i += 128) btm[i] = b_table[i * NH + h];

    const float* Qg = Qp + ((size_t)(b * LQ + m0)) * DM + h * DK;
    const float* Kg = Kp + ((size_t)(b * LK)) * DM + h * DK;
    const float* Vg = Vt + ((size_t)(b * DM + h * DK)) * LK;
    const unsigned short* BMg = bm + ((size_t)(b * LQ + m0)) * LK;

    // stage Q (64 rows x 64 floats, swizzled)
#pragma unroll
    for (int i = 0; i < 8; i++) {
        int gi = tid + i * 128;
        int r = gi >> 4, g = gi & 15;
        CP16(sQ + r * 256 + (((g ^ (r & 7)) << 4)), Qg + (size_t)r * DM + g * 4);
    }

#define STAGE_KV(IT, BUF) do {                                                 \
    const float* Ksrc_ = Kg + (size_t)((IT) * 64) * DM;                        \
    const float* Vsrc_ = Vg + (IT) * 64;                                       \
    const unsigned short* Bsrc_ = BMg + (IT) * 64;                             \
    _Pragma("unroll")                                                          \
    for (int i_ = 0; i_ < 8; i_++) {                                           \
        int gi_ = tid + i_ * 128;                                              \
        int r_ = gi_ >> 4, g_ = gi_ & 15;                                      \
        CP16(sKb[BUF] + r_ * 256 + (((g_ ^ (r_ & 7)) << 4)),                   \
             Ksrc_ + (size_t)r_ * DM + g_ * 4);                                \
    }                                                                          \
    _Pragma("unroll")                                                          \
    for (int i_ = 0; i_ < 8; i_++) {                                           \
        int gi_ = tid + i_ * 128;                                              \
        int r_ = gi_ >> 4, g_ = gi_ & 15;                                      \
        CP16(sVb[BUF] + r_ * 256 + (((g_ ^ (r_ & 7)) << 4)),                   \
             Vsrc_ + (size_t)r_ * LK + g_ * 4);                                \
    }                                                                          \
    _Pragma("unroll")                                                          \
    for (int i_ = 0; i_ < 4; i_++) {                                           \
        int gi_ = tid + i_ * 128;                                              \
        int r_ = gi_ >> 3, g_ = gi_ & 7;                                       \
        CP16(sBMb[BUF] + r_ * 128 + (((g_ ^ (r_ & 7)) << 4)),                  \
             Bsrc_ + (size_t)r_ * LK + g_ * 8);                                \
    }                                                                          \
} while (0)

    STAGE_KV(0, 0);
    CPCOMMIT;

    uint32_t aq[8][4];
    float oacc[8][4];
#pragma unroll
    for (int nf = 0; nf < 8; nf++)
#pragma unroll
        for (int r = 0; r < 4; r++) oacc[nf][r] = 0.f;
    float mr0 = -CUDART_INF_F, mr1 = -CUDART_INF_F;
    float sr0 = 0.f, sr1 = 0.f;

    const int lr = mw + (l >> 2);          // local query row (0..63)
    const uint32_t lrx = (uint32_t)(lr & 7);

    int buf = 0;
    for (int it = 0; it < LK / 64; ++it) {
        if (it + 1 < LK / 64) { STAGE_KV(it + 1, buf ^ 1); CPCOMMIT; CPWAIT1; }
        else                  { CPWAIT0; }
        __syncthreads();

        if (it == 0) {
#pragma unroll
            for (int kg = 0; kg < 8; kg++) {
                uint32_t ad = sQ + (mw + (l & 15)) * 256 +
                              (((2 * kg + (l >> 4)) ^ lx) << 4);
                LDSM4(aq[kg][0], aq[kg][1], aq[kg][2], aq[kg][3], ad);
            }
        }

        // ---- S = Q K^T ----
        float sval[8][4];
#pragma unroll
        for (int nf = 0; nf < 8; nf++)
#pragma unroll
            for (int r = 0; r < 4; r++) sval[nf][r] = 0.f;

#pragma unroll
        for (int s = 0; s < 8; s += 2) {
#pragma unroll
            for (int nf = 0; nf < 8; nf++) {
                uint32_t kb[4];
                uint32_t ad = sKb[buf] + (nf * 8 + lx) * 256 +
                              (((2 * s + ((l >> 3) & 3)) ^ lx) << 4);
                LDSM4(kb[0], kb[1], kb[2], kb[3], ad);
                MMA_TF32(sval[nf], aq[s],     kb[0], kb[1]);
                MMA_TF32(sval[nf], aq[s + 1], kb[2], kb[3]);
            }
        }

        // ---- scale + bias gather + mask (packed uint16 from smem) ----
        {
            const uint32_t base = bmOff[buf] / 4 + lr * 32 + (l & 3);
            const uint32_t* sm32 = (const uint32_t*)smem;
#pragma unroll
            for (int nf = 0; nf < 8; nf++) {
                uint32_t o = base + (((uint32_t)nf ^ lrx) << 2);
                uint32_t e01 = sm32[o];
                uint32_t e23 = sm32[o + 8 * 32];
                uint32_t e0 = e01 & 0xffffu, e1 = e01 >> 16;
                uint32_t e2 = e23 & 0xffffu, e3 = e23 >> 16;
                sval[nf][0] = (e0 & 0x8000u) ? sval[nf][0] * 0.125f + btm[e0 & 0x3ffu] : -1e9f;
                sval[nf][1] = (e1 & 0x8000u) ? sval[nf][1] * 0.125f + btm[e1 & 0x3ffu] : -1e9f;
                sval[nf][2] = (e2 & 0x8000u) ? sval[nf][2] * 0.125f + btm[e2 & 0x3ffu] : -1e9f;
                sval[nf][3] = (e3 & 0x8000u) ? sval[nf][3] * 0.125f + btm[e3 & 0x3ffu] : -1e9f;
            }
        }

        // ---- online softmax ----
        float tm0 = -CUDART_INF_F, tm1 = -CUDART_INF_F;
#pragma unroll
        for (int nf = 0; nf < 8; nf++) {
            tm0 = fmaxf(tm0, fmaxf(sval[nf][0], sval[nf][1]));
            tm1 = fmaxf(tm1, fmaxf(sval[nf][2], sval[nf][3]));
        }
#pragma unroll
        for (int o = 1; o < 4; o <<= 1) {
            tm0 = fmaxf(tm0, __shfl_xor_sync(0xffffffffu, tm0, o));
            tm1 = fmaxf(tm1, __shfl_xor_sync(0xffffffffu, tm1, o));
        }
        float mn0 = fmaxf(mr0, tm0), mn1 = fmaxf(mr1, tm1);
        float al0 = __expf(mr0 - mn0), al1 = __expf(mr1 - mn1);
        mr0 = mn0; mr1 = mn1;

        float ts0 = 0.f, ts1 = 0.f;
#pragma unroll
        for (int nf = 0; nf < 8; nf++) {
            sval[nf][0] = __expf(sval[nf][0] - mn0);
            sval[nf][1] = __expf(sval[nf][1] - mn0);
            sval[nf][2] = __expf(sval[nf][2] - mn1);
            sval[nf][3] = __expf(sval[nf][3] - mn1);
            ts0 += sval[nf][0] + sval[nf][1];
            ts1 += sval[nf][2] + sval[nf][3];
        }
#pragma unroll
        for (int o = 1; o < 4; o <<= 1) {
            ts0 += __shfl_xor_sync(0xffffffffu, ts0, o);
            ts1 += __shfl_xor_sync(0xffffffffu, ts1, o);
        }
        sr0 = sr0 * al0 + ts0;
        sr1 = sr1 * al1 + ts1;
#pragma unroll
        for (int nf = 0; nf < 8; nf++) {
            oacc[nf][0] *= al0; oacc[nf][1] *= al0;
            oacc[nf][2] *= al1; oacc[nf][3] *= al1;
        }

        // ---- P -> per-warp patch (aliases this warp's Q rows) ----
        {
            const uint32_t pb = sQ + w * 4096;
            const int rs0 = l >> 2;
            const uint32_t boff = ((l & 1) << 3);
            __syncwarp();
#pragma unroll
            for (int nf = 0; nf < 8; nf++) {
                int g = nf * 2 + ((l & 3) >> 1);
                uint32_t a0 = pb + rs0 * 256 + (((g ^ rs0) << 4)) + boff;
                uint32_t a1 = pb + (rs0 + 8) * 256 + (((g ^ rs0) << 4)) + boff;
                float2 p0 = { sval[nf][0], sval[nf][1] };
                float2 p1 = { sval[nf][2], sval[nf][3] };
                *(float2*)(smem + ((a0 - sb) >> 2)) = p0;
                *(float2*)(smem + ((a1 - sb) >> 2)) = p1;
            }
            __syncwarp();
        }

        uint32_t pa[8][4];
#pragma unroll
        for (int kg = 0; kg < 8; kg++) {
            uint32_t ad = sQ + w * 4096 + (l & 15) * 256 +
                          (((2 * kg + (l >> 4)) ^ lx) << 4);
            LDSM4(pa[kg][0], pa[kg][1], pa[kg][2], pa[kg][3], ad);
            CVT_TF32(pa[kg][0]); CVT_TF32(pa[kg][1]);
            CVT_TF32(pa[kg][2]); CVT_TF32(pa[kg][3]);
        }

        // ---- O += P V ----
#pragma unroll
        for (int s = 0; s < 8; s += 2) {
#pragma unroll
            for (int nf = 0; nf < 8; nf++) {
                uint32_t bv[4];
                uint32_t ad = sVb[buf] + (nf * 8 + lx) * 256 +
                              (((2 * s + ((l >> 3) & 3)) ^ lx) << 4);
                LDSM4(bv[0], bv[1], bv[2], bv[3], ad);
                MMA_TF32(oacc[nf], pa[s],     bv[0], bv[1]);
                MMA_TF32(oacc[nf], pa[s + 1], bv[2], bv[3]);
            }
        }

        __syncthreads();
        buf ^= 1;
    }
#undef STAGE_KV

    // ---- write O (rounded to tf32 for the output projection) ----
    {
        const float i0 = 1.f / sr0, i1 = 1.f / sr1;
        const int r0 = m0 + mw + (l >> 2);
#pragma unroll
        for (int nf = 0; nf < 8; nf++) {
            int col = h * DK + nf * 8 + (l & 3) * 2;
            float2 o0 = { rtf32(oacc[nf][0] * i0), rtf32(oacc[nf][1] * i0) };
            float2 o1 = { rtf32(oacc[nf][2] * i1), rtf32(oacc[nf][3] * i1) };
            *(float2*)&Ao[((size_t)(b * LQ + r0)) * DM + col]     = o0;
            *(float2*)&Ao[((size_t)(b * LQ + r0 + 8)) * DM + col] = o1;
        }
    }
}

// ---------------------------------------------------------------------------
extern "C" void kernel_launch(void* const* d_in, const int* in_sizes, int n_in,
                              void* d_out, int out_size)
{
    const float* q       = (const float*)d_in[0];
    const float* k       = (const float*)d_in[1];
    const float* v       = (const float*)d_in[2];
    const int*   b_idx   = (const int*)  d_in[3];
    const int*   mask    = (const int*)  d_in[4];
    const float* Wq      = (const float*)d_in[5];
    const float* bq      = (const float*)d_in[6];
    const float* Wk      = (const float*)d_in[7];
    const float* bk      = (const float*)d_in[8];
    const float* Wv      = (const float*)d_in[9];
    const float* bv      = (const float*)d_in[10];
    const float* Wo      = (const float*)d_in[11];
    const float* bo      = (const float*)d_in[12];
    const float* b_table = (const float*)d_in[13];
    float* out = (float*)d_out;

    void *Qp_, *Kp_, *Vp_, *Vt_, *Ao_, *Wr_, *bm_;
    cudaGetSymbolAddress(&Qp_, g_Qp);
    cudaGetSymbolAddress(&Kp_, g_Kp);
    cudaGetSymbolAddress(&Vp_, g_Vp);
    cudaGetSymbolAddress(&Vt_, g_Vt);
    cudaGetSymbolAddress(&Ao_, g_Ao);
    cudaGetSymbolAddress(&Wr_, g_Wr);
    cudaGetSymbolAddress(&bm_, g_bm);
    float* Qp = (float*)Qp_;
    float* Kp = (float*)Kp_;
    float* Vp = (float*)Vp_;
    float* Vt = (float*)Vt_;
    float* Ao = (float*)Ao_;
    float* Wr = (float*)Wr_;
    unsigned short* bm = (unsigned short*)bm_;

    static int attr_set = 0;
    if (!attr_set) {
        cudaFuncSetAttribute(gemm_bt_tf32<1,1>, cudaFuncAttributeMaxDynamicSharedMemorySize, 65536);
        cudaFuncSetAttribute(gemm_bt_tf32<0,0>, cudaFuncAttributeMaxDynamicSharedMemorySize, 65536);
        cudaFuncSetAttribute(flash_attn_tf32,   cudaFuncAttributeMaxDynamicSharedMemorySize, 101904);
        attr_set = 1;
    }

    // precompute: rounded weights + packed bias/mask
    const int NW4 = DM * DM / 4;
    const int NB4 = BSZ * LQ * LK / 4;
    round_tf32_kernel<<<(NW4 + 255) / 256, 256>>>((const float4*)Wq, (float4*)(Wr + 0 * DM * DM), NW4);
    round_tf32_kernel<<<(NW4 + 255) / 256, 256>>>((const float4*)Wk, (float4*)(Wr + 1 * DM * DM), NW4);
    round_tf32_kernel<<<(NW4 + 255) / 256, 256>>>((const float4*)Wv, (float4*)(Wr + 2 * DM * DM), NW4);
    round_tf32_kernel<<<(NW4 + 255) / 256, 256>>>((const float4*)Wo, (float4*)(Wr + 3 * DM * DM), NW4);
    pack_bm_kernel<<<(NB4 + 255) / 256, 256>>>((const int4*)b_idx, (const int4*)mask, (ushort4*)bm, NB4);

    // projections (A converted in-loop; outputs rounded)
    gemm_bt_tf32<1,1><<<dim3(DM / 128, (BSZ * LQ) / 128), 256, 65536>>>(q, Wr + 0 * DM * DM, bq, Qp, BSZ * LQ, DM, DM);
    gemm_bt_tf32<1,1><<<dim3(DM / 128, (BSZ * LK) / 128), 256, 65536>>>(k, Wr + 1 * DM * DM, bk, Kp, BSZ * LK, DM, DM);
    gemm_bt_tf32<1,1><<<dim3(DM / 128, (BSZ * LK) / 128), 256, 65536>>>(v, Wr + 2 * DM * DM, bv, Vp, BSZ * LK, DM, DM);
    vtrans_kernel<<<dim3(LK / 32, DM / 32, BSZ), 256>>>(Vp, Vt);

    // fused attention (h fastest for packed bm L2 reuse)
    flash_attn_tf32<<<dim3(NH, LQ / 64, BSZ), 128, 101904>>>(
        Qp, Kp, Vt, bm, b_table, Ao);

    // output projection (A pre-rounded at flash epilogue; output fp32)
    gemm_bt_tf32<0,0><<<dim3(DM / 128, (BSZ * LQ) / 128), 256, 65536>>>(Ao, Wr + 3 * DM * DM, bo, out, BSZ * LQ, DM, DM);
}

// round 7
// speedup vs baseline: 8.7270x; 1.0358x over previous
#include <cuda_runtime.h>
#include <cstdint>
#include <math_constants.h>

#define BSZ 4
#define LQ  512
#define LK  2048
#define DM  1024
#define NH  16
#define DK  64
#define VOCAB_B 900

// ---------------- scratch (static device memory; no runtime alloc) ----------
__device__ float g_Qp[BSZ * LQ * DM];
__device__ float g_Kp[BSZ * LK * DM];
__device__ float g_Vt[BSZ * DM * LK];                  // V projected+transposed
__device__ float g_Ao[BSZ * LQ * DM];
__device__ unsigned short g_bm[BSZ * LQ * LK];         // packed b_idx|mask<<15

// ---------------- PTX helpers ----------------------------------------------
__device__ __forceinline__ uint32_t s_u32(const void* p) {
    uint32_t a;
    asm("{.reg .u64 t; cvta.to.shared.u64 t, %1; cvt.u32.u64 %0, t;}"
        : "=r"(a) : "l"(p));
    return a;
}

__device__ __forceinline__ float rtf32(float x) {
    uint32_t u = __float_as_uint(x);
    asm("cvt.rna.tf32.f32 %0,%0;" : "+r"(u));
    return __uint_as_float(u);
}

#define LDSM4(R0,R1,R2,R3,ADDR) \
    asm volatile("ldmatrix.sync.aligned.m8n8.x4.shared.b16 {%0,%1,%2,%3},[%4];" \
        : "=r"(R0),"=r"(R1),"=r"(R2),"=r"(R3) : "r"(ADDR))

#define CVT_TF32(T) asm volatile("cvt.rna.tf32.f32 %0,%0;" : "+r"(T))

#define MMA_TF32(D,A,B0,B1) \
    asm volatile("mma.sync.aligned.m16n8k8.row.col.f32.tf32.tf32.f32 " \
        "{%0,%1,%2,%3},{%4,%5,%6,%7},{%8,%9},{%0,%1,%2,%3};" \
        : "+f"(D[0]),"+f"(D[1]),"+f"(D[2]),"+f"(D[3]) \
        : "r"(A[0]),"r"(A[1]),"r"(A[2]),"r"(A[3]),"r"(B0),"r"(B1))

#define CP16(DST,SRC) \
    asm volatile("cp.async.cg.shared.global [%0],[%1],16;" :: "r"(DST),"l"(SRC))
#define CPCOMMIT  asm volatile("cp.async.commit_group;")
#define CPWAIT0   asm volatile("cp.async.wait_group 0;")
#define CPWAIT1   asm volatile("cp.async.wait_group 1;")

// ============================================================================
// pack b_idx + mask -> uint16 (idx | mask<<15), 4x ILP grid-strided
// ============================================================================
__device__ __forceinline__ ushort4 pack4(int4 ix, int4 mk) {
    ushort4 o;
    o.x = (unsigned short)(ix.x | (mk.x << 15));
    o.y = (unsigned short)(ix.y | (mk.y << 15));
    o.z = (unsigned short)(ix.z | (mk.z << 15));
    o.w = (unsigned short)(ix.w | (mk.w << 15));
    return o;
}
__global__ __launch_bounds__(256) void pack_bm_kernel(
    const int4* __restrict__ b_idx, const int4* __restrict__ mask,
    ushort4* __restrict__ bm, int n4)
{
    const int s = gridDim.x * 256;
    int i = blockIdx.x * 256 + threadIdx.x;
    if (i + 3 * s < n4) {
        int4 a0 = b_idx[i],         a1 = b_idx[i + s],
             a2 = b_idx[i + 2 * s], a3 = b_idx[i + 3 * s];
        int4 m0 = mask[i],          m1 = mask[i + s],
             m2 = mask[i + 2 * s],  m3 = mask[i + 3 * s];
        bm[i]         = pack4(a0, m0);
        bm[i + s]     = pack4(a1, m1);
        bm[i + 2 * s] = pack4(a2, m2);
        bm[i + 3 * s] = pack4(a3, m3);
    } else {
        for (; i < n4; i += s) bm[i] = pack4(b_idx[i], mask[i]);
    }
}

// ============================================================================
// tf32 GEMM: C = A @ B^T + bias.
// CVTA/CVTB: round A/B fragments in-loop. RND: round outputs.
// TRANSV: write output TRANSPOSED to Vt[b][n][m%LK] (rounded), via smem.
// ============================================================================
template<int CVTA, int CVTB, int RND, int TRANSV>
__global__ __launch_bounds__(256, 2) void gemm_bt_tf32(
    const float* __restrict__ A, const float* __restrict__ B,
    const float* __restrict__ bias, float* __restrict__ C,
    int M, int N, int K)
{
    extern __shared__ float smem[];
    const uint32_t sbase = s_u32(smem);
    const int tid = threadIdx.x;
    const int m0 = blockIdx.y * 128, n0 = blockIdx.x * 128;
    const int l  = tid & 31, w = tid >> 5;
    const int mw = (w >> 2) * 64, nw = (w & 3) * 32;
    const int lrow = l & 15, lq = l >> 4, lx = l & 7;
    const int sm = tid >> 3, sg = tid & 7;

    float acc[4][4][4];
#pragma unroll
    for (int i = 0; i < 4; i++)
#pragma unroll
        for (int j = 0; j < 4; j++)
#pragma unroll
            for (int r = 0; r < 4; r++) acc[i][j][r] = 0.f;

    const int NIT = K >> 5;

#define STAGE_G(IT, BUF) do {                                                  \
    uint32_t sA_ = sbase + (BUF) * 32768;                                      \
    uint32_t sB_ = sA_ + 16384;                                                \
    const float* Ag_ = A + (size_t)(m0) * K + (IT) * 32;                       \
    const float* Bg_ = B + (size_t)(n0) * K + (IT) * 32;                       \
    _Pragma("unroll")                                                          \
    for (int i_ = 0; i_ < 4; i_++) {                                           \
        int r_ = sm + i_ * 32;                                                 \
        CP16(sA_ + r_ * 128 + (((sg ^ (r_ & 7)) << 4)),                        \
             Ag_ + (size_t)r_ * K + sg * 4);                                   \
    }                                                                          \
    _Pragma("unroll")                                                          \
    for (int i_ = 0; i_ < 4; i_++) {                                           \
        int r_ = sm + i_ * 32;                                                 \
        CP16(sB_ + r_ * 128 + (((sg ^ (r_ & 7)) << 4)),                        \
             Bg_ + (size_t)r_ * K + sg * 4);                                   \
    }                                                                          \
} while (0)

    STAGE_G(0, 0);
    CPCOMMIT;

    int buf = 0;
    for (int it = 0; it < NIT; ++it) {
        if (it + 1 < NIT) { STAGE_G(it + 1, buf ^ 1); CPCOMMIT; CPWAIT1; }
        else              { CPWAIT0; }
        __syncthreads();

        const uint32_t sA = sbase + buf * 32768;
        const uint32_t sB = sA + 16384;
        const uint32_t aAdr0 = sA + (mw + lrow) * 128;
        const uint32_t bAdr0 = sB + (nw + (l & 7)) * 128;

#pragma unroll
        for (int s = 0; s < 4; s += 2) {
            uint32_t b[4][4];
#pragma unroll
            for (int nf = 0; nf < 4; nf++) {
                uint32_t ad = bAdr0 + nf * 1024 +
                              (((2 * s + ((l >> 3) & 3)) ^ lx) << 4);
                LDSM4(b[nf][0], b[nf][1], b[nf][2], b[nf][3], ad);
                if (CVTB) {
                    CVT_TF32(b[nf][0]); CVT_TF32(b[nf][1]);
                    CVT_TF32(b[nf][2]); CVT_TF32(b[nf][3]);
                }
            }
#pragma unroll
            for (int ss = 0; ss < 2; ss++) {
                uint32_t a[4][4];
#pragma unroll
                for (int mf = 0; mf < 4; mf++) {
                    uint32_t ad = aAdr0 + mf * 2048 +
                                  (((2 * (s + ss) + lq) ^ lx) << 4);
                    LDSM4(a[mf][0], a[mf][1], a[mf][2], a[mf][3], ad);
                    if (CVTA) {
                        CVT_TF32(a[mf][0]); CVT_TF32(a[mf][1]);
                        CVT_TF32(a[mf][2]); CVT_TF32(a[mf][3]);
                    }
                }
#pragma unroll
                for (int mf = 0; mf < 4; mf++)
#pragma unroll
                    for (int nf = 0; nf < 4; nf++)
                        MMA_TF32(acc[mf][nf], a[mf], b[nf][2 * ss], b[nf][2 * ss + 1]);
            }
        }
        __syncthreads();
        buf ^= 1;
    }
#undef STAGE_G

    if (TRANSV) {
        // stage rounded acc+bias into smem as [n][m] (pitch 132), then write
        // Vt[b][n0+n][kb+m] coalesced along m.
        __syncthreads();
#pragma unroll
        for (int mf = 0; mf < 4; mf++) {
            int mloc = mw + mf * 16 + (l >> 2);
#pragma unroll
            for (int nf = 0; nf < 4; nf++) {
                int nloc = nw + nf * 8 + (l & 3) * 2;
                float2 bb = *(const float2*)&bias[n0 + nloc];
                smem[(nloc)     * 132 + mloc]     = rtf32(acc[mf][nf][0] + bb.x);
                smem[(nloc + 1) * 132 + mloc]     = rtf32(acc[mf][nf][1] + bb.y);
                smem[(nloc)     * 132 + mloc + 8] = rtf32(acc[mf][nf][2] + bb.x);
                smem[(nloc + 1) * 132 + mloc + 8] = rtf32(acc[mf][nf][3] + bb.y);
            }
        }
        __syncthreads();
        const int bb_ = m0 / LK;
        const int kb_ = m0 % LK;
#pragma unroll
        for (int i = 0; i < 16; i++) {
            int n = w * 16 + i;
            float4 vv = *(const float4*)&smem[n * 132 + 4 * l];
            *(float4*)&C[((size_t)(bb_ * DM + n0 + n)) * LK + kb_ + 4 * l] = vv;
        }
    } else {
#pragma unroll
        for (int mf = 0; mf < 4; mf++) {
            int row = m0 + mw + mf * 16 + (l >> 2);
#pragma unroll
            for (int nf = 0; nf < 4; nf++) {
                int col = n0 + nw + nf * 8 + (l & 3) * 2;
                float2 bb = *(const float2*)&bias[col];
                float2 o0, o1;
                o0.x = acc[mf][nf][0] + bb.x; o0.y = acc[mf][nf][1] + bb.y;
                o1.x = acc[mf][nf][2] + bb.x; o1.y = acc[mf][nf][3] + bb.y;
                if (RND) {
                    o0.x = rtf32(o0.x); o0.y = rtf32(o0.y);
                    o1.x = rtf32(o1.x); o1.y = rtf32(o1.y);
                }
                *(float2*)&C[(size_t)row * N + col]       = o0;
                *(float2*)&C[(size_t)(row + 8) * N + col] = o1;
            }
        }
    }
}

// ============================================================================
// Fused flash attention. CTA: 64 queries, 4 warps, 2 CTAs/SM.
// bias/mask gathered from packed uint16 tile staged in smem.
// ============================================================================
__global__ __launch_bounds__(128, 2) void flash_attn_tf32(
    const float* __restrict__ Qp, const float* __restrict__ Kp,
    const float* __restrict__ Vt, const unsigned short* __restrict__ bm,
    const float* __restrict__ b_table, float* __restrict__ Ao)
{
    extern __shared__ float smem[];
    const uint32_t sb = s_u32(smem);
    const uint32_t sQ = sb;                       // aliased by P after Q consumed
    const uint32_t sKb[2]  = { sb + 16384, sb + 57344 };
    const uint32_t sVb[2]  = { sb + 32768, sb + 73728 };
    const uint32_t sBMb[2] = { sb + 49152, sb + 90112 };
    const uint32_t bmOff[2] = { 49152, 90112 };
    float* btm = smem + 98304 / 4;

    const int tid = threadIdx.x;
    const int h = blockIdx.x, b = blockIdx.z;
    const int m0 = blockIdx.y * 64;
    const int l = tid & 31, w = tid >> 5;
    const int mw = w * 16;
    const int lx = l & 7;

    for (int i = tid; i < VOCAB_B; i += 128) btm[i] = b_table[i * NH + h];

    const float* Qg = Qp + ((size_t)(b * LQ + m0)) * DM + h * DK;
    const float* Kg = Kp + ((size_t)(b * LK)) * DM + h * DK;
    const float* Vg = Vt + ((size_t)(b * DM + h * DK)) * LK;
    const unsigned short* BMg = bm + ((size_t)(b * LQ + m0)) * LK;

#pragma unroll
    for (int i = 0; i < 8; i++) {
        int gi = tid + i * 128;
        int r = gi >> 4, g = gi & 15;
        CP16(sQ + r * 256 + (((g ^ (r & 7)) << 4)), Qg + (size_t)r * DM + g * 4);
    }

#define STAGE_KV(IT, BUF) do {                                                 \
    const float* Ksrc_ = Kg + (size_t)((IT) * 64) * DM;                        \
    const float* Vsrc_ = Vg + (IT) * 64;                                       \
    const unsigned short* Bsrc_ = BMg + (IT) * 64;                             \
    _Pragma("unroll")                                                          \
    for (int i_ = 0; i_ < 8; i_++) {                                           \
        int gi_ = tid + i_ * 128;                                              \
        int r_ = gi_ >> 4, g_ = gi_ & 15;                                      \
        CP16(sKb[BUF] + r_ * 256 + (((g_ ^ (r_ & 7)) << 4)),                   \
             Ksrc_ + (size_t)r_ * DM + g_ * 4);                                \
    }                                                                          \
    _Pragma("unroll")                                                          \
    for (int i_ = 0; i_ < 8; i_++) {                                           \
        int gi_ = tid + i_ * 128;                                              \
        int r_ = gi_ >> 4, g_ = gi_ & 15;                                      \
        CP16(sVb[BUF] + r_ * 256 + (((g_ ^ (r_ & 7)) << 4)),                   \
             Vsrc_ + (size_t)r_ * LK + g_ * 4);                                \
    }                                                                          \
    _Pragma("unroll")                                                          \
    for (int i_ = 0; i_ < 4; i_++) {                                           \
        int gi_ = tid + i_ * 128;                                              \
        int r_ = gi_ >> 3, g_ = gi_ & 7;                                       \
        CP16(sBMb[BUF] + r_ * 128 + (((g_ ^ (r_ & 7)) << 4)),                  \
             Bsrc_ + (size_t)r_ * LK + g_ * 8);                                \
    }                                                                          \
} while (0)

    STAGE_KV(0, 0);
    CPCOMMIT;

    uint32_t aq[8][4];
    float oacc[8][4];
#pragma unroll
    for (int nf = 0; nf < 8; nf++)
#pragma unroll
        for (int r = 0; r < 4; r++) oacc[nf][r] = 0.f;
    float mr0 = -CUDART_INF_F, mr1 = -CUDART_INF_F;
    float sr0 = 0.f, sr1 = 0.f;

    const int lr = mw + (l >> 2);
    const uint32_t lrx = (uint32_t)(lr & 7);

    int buf = 0;
    for (int it = 0; it < LK / 64; ++it) {
        if (it + 1 < LK / 64) { STAGE_KV(it + 1, buf ^ 1); CPCOMMIT; CPWAIT1; }
        else                  { CPWAIT0; }
        __syncthreads();

        if (it == 0) {
#pragma unroll
            for (int kg = 0; kg < 8; kg++) {
                uint32_t ad = sQ + (mw + (l & 15)) * 256 +
                              (((2 * kg + (l >> 4)) ^ lx) << 4);
                LDSM4(aq[kg][0], aq[kg][1], aq[kg][2], aq[kg][3], ad);
            }
        }

        // ---- S = Q K^T ----
        float sval[8][4];
#pragma unroll
        for (int nf = 0; nf < 8; nf++)
#pragma unroll
            for (int r = 0; r < 4; r++) sval[nf][r] = 0.f;

#pragma unroll
        for (int s = 0; s < 8; s += 2) {
#pragma unroll
            for (int nf = 0; nf < 8; nf++) {
                uint32_t kb[4];
                uint32_t ad = sKb[buf] + (nf * 8 + lx) * 256 +
                              (((2 * s + ((l >> 3) & 3)) ^ lx) << 4);
                LDSM4(kb[0], kb[1], kb[2], kb[3], ad);
                MMA_TF32(sval[nf], aq[s],     kb[0], kb[1]);
                MMA_TF32(sval[nf], aq[s + 1], kb[2], kb[3]);
            }
        }

        // ---- scale + bias gather + mask ----
        {
            const uint32_t base = bmOff[buf] / 4 + lr * 32 + (l & 3);
            const uint32_t* sm32 = (const uint32_t*)smem;
#pragma unroll
            for (int nf = 0; nf < 8; nf++) {
                uint32_t o = base + (((uint32_t)nf ^ lrx) << 2);
                uint32_t e01 = sm32[o];
                uint32_t e23 = sm32[o + 8 * 32];
                uint32_t e0 = e01 & 0xffffu, e1 = e01 >> 16;
                uint32_t e2 = e23 & 0xffffu, e3 = e23 >> 16;
                sval[nf][0] = (e0 & 0x8000u) ? sval[nf][0] * 0.125f + btm[e0 & 0x3ffu] : -1e9f;
                sval[nf][1] = (e1 & 0x8000u) ? sval[nf][1] * 0.125f + btm[e1 & 0x3ffu] : -1e9f;
                sval[nf][2] = (e2 & 0x8000u) ? sval[nf][2] * 0.125f + btm[e2 & 0x3ffu] : -1e9f;
                sval[nf][3] = (e3 & 0x8000u) ? sval[nf][3] * 0.125f + btm[e3 & 0x3ffu] : -1e9f;
            }
        }

        // ---- online softmax ----
        float tm0 = -CUDART_INF_F, tm1 = -CUDART_INF_F;
#pragma unroll
        for (int nf = 0; nf < 8; nf++) {
            tm0 = fmaxf(tm0, fmaxf(sval[nf][0], sval[nf][1]));
            tm1 = fmaxf(tm1, fmaxf(sval[nf][2], sval[nf][3]));
        }
#pragma unroll
        for (int o = 1; o < 4; o <<= 1) {
            tm0 = fmaxf(tm0, __shfl_xor_sync(0xffffffffu, tm0, o));
            tm1 = fmaxf(tm1, __shfl_xor_sync(0xffffffffu, tm1, o));
        }
        float mn0 = fmaxf(mr0, tm0), mn1 = fmaxf(mr1, tm1);
        float al0 = __expf(mr0 - mn0), al1 = __expf(mr1 - mn1);
        mr0 = mn0; mr1 = mn1;

        float ts0 = 0.f, ts1 = 0.f;
#pragma unroll
        for (int nf = 0; nf < 8; nf++) {
            sval[nf][0] = __expf(sval[nf][0] - mn0);
            sval[nf][1] = __expf(sval[nf][1] - mn0);
            sval[nf][2] = __expf(sval[nf][2] - mn1);
            sval[nf][3] = __expf(sval[nf][3] - mn1);
            ts0 += sval[nf][0] + sval[nf][1];
            ts1 += sval[nf][2] + sval[nf][3];
        }
#pragma unroll
        for (int o = 1; o < 4; o <<= 1) {
            ts0 += __shfl_xor_sync(0xffffffffu, ts0, o);
            ts1 += __shfl_xor_sync(0xffffffffu, ts1, o);
        }
        sr0 = sr0 * al0 + ts0;
        sr1 = sr1 * al1 + ts1;
#pragma unroll
        for (int nf = 0; nf < 8; nf++) {
            oacc[nf][0] *= al0; oacc[nf][1] *= al0;
            oacc[nf][2] *= al1; oacc[nf][3] *= al1;
        }

        // ---- P -> per-warp patch (aliases this warp's Q rows) ----
        {
            const uint32_t pb = sQ + w * 4096;
            const int rs0 = l >> 2;
            const uint32_t boff = ((l & 1) << 3);
            __syncwarp();
#pragma unroll
            for (int nf = 0; nf < 8; nf++) {
                int g = nf * 2 + ((l & 3) >> 1);
                uint32_t a0 = pb + rs0 * 256 + (((g ^ rs0) << 4)) + boff;
                uint32_t a1 = pb + (rs0 + 8) * 256 + (((g ^ rs0) << 4)) + boff;
                float2 p0 = { sval[nf][0], sval[nf][1] };
                float2 p1 = { sval[nf][2], sval[nf][3] };
                *(float2*)(smem + ((a0 - sb) >> 2)) = p0;
                *(float2*)(smem + ((a1 - sb) >> 2)) = p1;
            }
            __syncwarp();
        }

        uint32_t pa[8][4];
#pragma unroll
        for (int kg = 0; kg < 8; kg++) {
            uint32_t ad = sQ + w * 4096 + (l & 15) * 256 +
                          (((2 * kg + (l >> 4)) ^ lx) << 4);
            LDSM4(pa[kg][0], pa[kg][1], pa[kg][2], pa[kg][3], ad);
            CVT_TF32(pa[kg][0]); CVT_TF32(pa[kg][1]);
            CVT_TF32(pa[kg][2]); CVT_TF32(pa[kg][3]);
        }

        // ---- O += P V ----
#pragma unroll
        for (int s = 0; s < 8; s += 2) {
#pragma unroll
            for (int nf = 0; nf < 8; nf++) {
                uint32_t bv[4];
                uint32_t ad = sVb[buf] + (nf * 8 + lx) * 256 +
                              (((2 * s + ((l >> 3) & 3)) ^ lx) << 4);
                LDSM4(bv[0], bv[1], bv[2], bv[3], ad);
                MMA_TF32(oacc[nf], pa[s],     bv[0], bv[1]);
                MMA_TF32(oacc[nf], pa[s + 1], bv[2], bv[3]);
            }
        }

        __syncthreads();
        buf ^= 1;
    }
#undef STAGE_KV

    // ---- write O (rounded to tf32 for the output projection) ----
    {
        const float i0 = 1.f / sr0, i1 = 1.f / sr1;
        const int r0 = m0 + mw + (l >> 2);
#pragma unroll
        for (int nf = 0; nf < 8; nf++) {
            int col = h * DK + nf * 8 + (l & 3) * 2;
            float2 o0 = { rtf32(oacc[nf][0] * i0), rtf32(oacc[nf][1] * i0) };
            float2 o1 = { rtf32(oacc[nf][2] * i1), rtf32(oacc[nf][3] * i1) };
            *(float2*)&Ao[((size_t)(b * LQ + r0)) * DM + col]     = o0;
            *(float2*)&Ao[((size_t)(b * LQ + r0 + 8)) * DM + col] = o1;
        }
    }
}

// ---------------------------------------------------------------------------
extern "C" void kernel_launch(void* const* d_in, const int* in_sizes, int n_in,
                              void* d_out, int out_size)
{
    const float* q       = (const float*)d_in[0];
    const float* k       = (const float*)d_in[1];
    const float* v       = (const float*)d_in[2];
    const int*   b_idx   = (const int*)  d_in[3];
    const int*   mask    = (const int*)  d_in[4];
    const float* Wq      = (const float*)d_in[5];
    const float* bq      = (const float*)d_in[6];
    const float* Wk      = (const float*)d_in[7];
    const float* bk      = (const float*)d_in[8];
    const float* Wv      = (const float*)d_in[9];
    const float* bv      = (const float*)d_in[10];
    const float* Wo      = (const float*)d_in[11];
    const float* bo      = (const float*)d_in[12];
    const float* b_table = (const float*)d_in[13];
    float* out = (float*)d_out;

    void *Qp_, *Kp_, *Vt_, *Ao_, *bm_;
    cudaGetSymbolAddress(&Qp_, g_Qp);
    cudaGetSymbolAddress(&Kp_, g_Kp);
    cudaGetSymbolAddress(&Vt_, g_Vt);
    cudaGetSymbolAddress(&Ao_, g_Ao);
    cudaGetSymbolAddress(&bm_, g_bm);
    float* Qp = (float*)Qp_;
    float* Kp = (float*)Kp_;
    float* Vt = (float*)Vt_;
    float* Ao = (float*)Ao_;
    unsigned short* bm = (unsigned short*)bm_;

    static int attr_set = 0;
    if (!attr_set) {
        cudaFuncSetAttribute((const void*)gemm_bt_tf32<1,1,1,0>, cudaFuncAttributeMaxDynamicSharedMemorySize, 65536);
        cudaFuncSetAttribute((const void*)gemm_bt_tf32<1,1,1,1>, cudaFuncAttributeMaxDynamicSharedMemorySize, 69632);
        cudaFuncSetAttribute((const void*)gemm_bt_tf32<0,1,0,0>, cudaFuncAttributeMaxDynamicSharedMemorySize, 65536);
        cudaFuncSetAttribute((const void*)flash_attn_tf32,       cudaFuncAttributeMaxDynamicSharedMemorySize, 101904);
        attr_set = 1;
    }

    // pack bias/mask (h-invariant; L2-resident for flash)
    const int NB4 = BSZ * LQ * LK / 4;          // 1048576
    pack_bm_kernel<<<1024, 256>>>((const int4*)b_idx, (const int4*)mask, (ushort4*)bm, NB4);

    // projections (operands rounded in-loop; outputs rounded)
    gemm_bt_tf32<1,1,1,0><<<dim3(DM / 128, (BSZ * LQ) / 128), 256, 65536>>>(q, Wq, bq, Qp, BSZ * LQ, DM, DM);
    gemm_bt_tf32<1,1,1,0><<<dim3(DM / 128, (BSZ * LK) / 128), 256, 65536>>>(k, Wk, bk, Kp, BSZ * LK, DM, DM);
    // V projection writes transposed Vt directly
    gemm_bt_tf32<1,1,1,1><<<dim3(DM / 128, (BSZ * LK) / 128), 256, 69632>>>(v, Wv, bv, Vt, BSZ * LK, DM, DM);

    // fused attention (h fastest for packed bm L2 reuse)
    flash_attn_tf32<<<dim3(NH, LQ / 64, BSZ), 128, 101904>>>(
        Qp, Kp, Vt, bm, b_table, Ao);

    // output projection (A pre-rounded; B rounded in-loop; output fp32)
    gemm_bt_tf32<0,1,0,0><<<dim3(DM / 128, (BSZ * LQ) / 128), 256, 65536>>>(Ao, Wo, bo, out, BSZ * LQ, DM, DM);
}